// round 15
// baseline (speedup 1.0000x reference)
#include <cuda_runtime.h>
#include <cuda_fp16.h>
#include <math.h>
#include <stdint.h>

// ---------------------------------------------------------------------------
// Problem constants (GRID fixed: [[1,48,48],[1,32,64],[2,24,40]])
// ---------------------------------------------------------------------------
#define NTOK    6272
#define DMODEL  1152
#define HEADS   16
#define HDIM    72
#define IDIM    4304
#define DOUT    2048
#define MROWS   1568
#define MD4     4608
#define QKVW    3456
#define CIN     1536

// ---------------------------------------------------------------------------
// Scratch buffers
// ---------------------------------------------------------------------------
__device__ float  g_x    [NTOK * DMODEL];        // residual (fp32)
__device__ __half g_pix  [NTOK * CIN];           // pixel fp16
__device__ __half g_hh   [NTOK * DMODEL];        // LN out fp16
__device__ __half g_qkvh [NTOK * QKVW];          // qkv fp16
__device__ __half g_attnh[NTOK * DMODEL];        // attn out fp16
__device__ __half g_mlph [NTOK * IDIM];          // mlp hidden fp16
__device__ float  g_cos  [NTOK * 36];
__device__ float  g_sin  [NTOK * 36];

// fp16 weights, natural [K,N] layout (no transpose)
#define SZ_PATCH (1536ULL * 1152)
#define SZ_QKV   (1152ULL * 3456)
#define SZ_PROJ  (1152ULL * 1152)
#define SZ_FC1   (1152ULL * 4304)
#define SZ_FC2   (4304ULL * 1152)
#define SZ_MFC1  (4608ULL * 4608)
#define SZ_MFC2  (4608ULL * 2048)
#define OFF_PATCH 0ULL
#define OFF_QKV   (OFF_PATCH + SZ_PATCH)
#define OFF_PROJ  (OFF_QKV + 2 * SZ_QKV)
#define OFF_FC1   (OFF_PROJ + 2 * SZ_PROJ)
#define OFF_FC2   (OFF_FC1 + 2 * SZ_FC1)
#define OFF_MFC1  (OFF_FC2 + 2 * SZ_FC2)
#define OFF_MFC2  (OFF_MFC1 + SZ_MFC1)
#define WT_TOTAL  (OFF_MFC2 + SZ_MFC2)
__device__ __half g_wt[WT_TOTAL];

// ---------------------------------------------------------------------------
__device__ __forceinline__ void token_pos(int n, int& row, int& col, int& ih, int& iw)
{
    int local, h, w;
    if (n < 2304)      { local = n;          h = 48; w = 48; }
    else if (n < 4352) { local = n - 2304;   h = 32; w = 64; }
    else               { local = n - 4352;   h = 24; w = 40; }
    int rem = local % (h * w);
    int wb_cnt = w >> 1;
    int blk = rem >> 2, within = rem & 3;
    int hb = blk / wb_cnt, wb = blk % wb_cnt;
    row = hb * 2 + (within >> 1);
    col = wb * 2 + (within & 1);
    ih = h; iw = w;
}

// RoPE tables, fp32 math only
__global__ void cossin_kernel()
{
    int idx = blockIdx.x * blockDim.x + threadIdx.x;
    if (idx >= NTOK * 36) return;
    int n = idx / 36, d = idx % 36;
    int row, col, ih, iw;
    token_pos(n, row, col, ih, iw);
    int j = (d < 18) ? d : d - 18;
    float p = (d < 18) ? (float)row : (float)col;
    float inv = __expf(-(float)j * 0.5117865387079628f);
    float ang = p * inv;
    g_cos[idx] = cosf(ang);
    g_sin[idx] = sinf(ang);
}

// ---------------------------------------------------------------------------
// Fused fp32->fp16 convert for ALL prep streams in one launch.
// ---------------------------------------------------------------------------
#define NSEG 13
struct ConvJobs {
    const float4* src[NSEG];
    uint2*        dst[NSEG];
    int           off[NSEG + 1];
};

__global__ void convall(ConvJobs J, int total)
{
    int i = blockIdx.x * blockDim.x + threadIdx.x;
    if (i >= total) return;
    int s = 0;
#pragma unroll
    for (int k = 1; k < NSEG; k++) s += (i >= J.off[k]) ? 1 : 0;
    int local = i - J.off[s];
    float4 v = J.src[s][local];
    __half2 lo = __floats2half2_rn(v.x, v.y);
    __half2 hi = __floats2half2_rn(v.z, v.w);
    J.dst[s][local] =
        make_uint2(*reinterpret_cast<uint32_t*>(&lo), *reinterpret_cast<uint32_t*>(&hi));
}

__device__ __forceinline__ float warp_sum(float v)
{
#pragma unroll
    for (int o = 16; o > 0; o >>= 1) v += __shfl_xor_sync(0xffffffffu, v, o);
    return v;
}

// LayerNorm fp32 in -> fp16 out, vectorized (one float4 per thread; D=1152=288*4)
__global__ void ln_h(const float* __restrict__ in, __half* __restrict__ out,
                     const float* __restrict__ s, const float* __restrict__ b)
{
    __shared__ float sh[9];
    __shared__ float stat[2];
    int n = blockIdx.x;
    const float4* xr4 = reinterpret_cast<const float4*>(in + (size_t)n * DMODEL);
    int t = threadIdx.x, wid = t >> 5, lane = t & 31;

    float4 v = xr4[t];
    float lsum = v.x + v.y + v.z + v.w;
    float ws = warp_sum(lsum);
    if (lane == 0) sh[wid] = ws;
    __syncthreads();
    if (t == 0) {
        float tot = 0.f;
#pragma unroll
        for (int i = 0; i < 9; i++) tot += sh[i];
        stat[0] = tot * (1.0f / DMODEL);
    }
    __syncthreads();
    float mu = stat[0];
    float d0 = v.x - mu, d1 = v.y - mu, d2 = v.z - mu, d3 = v.w - mu;
    float lvar = d0 * d0 + d1 * d1 + d2 * d2 + d3 * d3;
    ws = warp_sum(lvar);
    __syncthreads();
    if (lane == 0) sh[wid] = ws;
    __syncthreads();
    if (t == 0) {
        float tot = 0.f;
#pragma unroll
        for (int i = 0; i < 9; i++) tot += sh[i];
        stat[1] = rsqrtf(tot * (1.0f / DMODEL) + 1e-6f);
    }
    __syncthreads();
    float r = stat[1];
    float4 s4 = reinterpret_cast<const float4*>(s)[t];
    float4 b4 = reinterpret_cast<const float4*>(b)[t];
    __half2 p0 = __floats2half2_rn(d0 * r * s4.x + b4.x, d1 * r * s4.y + b4.y);
    __half2 p1 = __floats2half2_rn(d2 * r * s4.z + b4.z, d3 * r * s4.w + b4.w);
    reinterpret_cast<uint2*>(out + (size_t)n * DMODEL)[t] =
        make_uint2(*reinterpret_cast<uint32_t*>(&p0), *reinterpret_cast<uint32_t*>(&p1));
}

// RoPE in-place on fp16 qkv
__global__ void rope_h()
{
    int n = blockIdx.x;
    int t = threadIdx.x;
    int h = t / 36, d = t % 36;
    float c = g_cos[n * 36 + d];
    float s = g_sin[n * 36 + d];
    __half* q = g_qkvh + (size_t)n * QKVW + h * HDIM;
    __half* k = q + DMODEL;
    float q0 = __half2float(q[d]), q1 = __half2float(q[d + 36]);
    q[d]      = __float2half_rn(q0 * c - q1 * s);
    q[d + 36] = __float2half_rn(q1 * c + q0 * s);
    float k0 = __half2float(k[d]), k1 = __half2float(k[d + 36]);
    k[d]      = __float2half_rn(k0 * c - k1 * s);
    k[d + 36] = __float2half_rn(k1 * c + k0 * s);
}

// ---------------------------------------------------------------------------
// mma / misc helpers
// ---------------------------------------------------------------------------
__device__ __forceinline__ void mma_f16(float c[4],
                                        uint32_t a0, uint32_t a1, uint32_t a2, uint32_t a3,
                                        uint32_t b0, uint32_t b1)
{
    asm volatile(
        "mma.sync.aligned.m16n8k16.row.col.f32.f16.f16.f32 "
        "{%0,%1,%2,%3}, {%4,%5,%6,%7}, {%8,%9}, {%0,%1,%2,%3};\n"
        : "+f"(c[0]), "+f"(c[1]), "+f"(c[2]), "+f"(c[3])
        : "r"(a0), "r"(a1), "r"(a2), "r"(a3), "r"(b0), "r"(b1));
}

// fast gelu: HW tanh approx (MUFU.TANH)
__device__ __forceinline__ float gelu_tanh(float x)
{
    float u = 0.7978845608028654f * (x + 0.044715f * x * x * x);
    float t;
    asm("tanh.approx.f32 %0, %1;" : "=f"(t) : "f"(u));
    return 0.5f * x * (1.f + t);
}

__device__ __forceinline__ uint32_t pack_h2(float lo, float hi)
{
    __half2 h = __floats2half2_rn(lo, hi);
    return *reinterpret_cast<uint32_t*>(&h);
}

// ---------------------------------------------------------------------------
// GEMM v4: A fp16 [M,K] row-major, B fp16 [K,N] row-major, C fp32 or fp16.
//   Block 128x128, BK=32, 4 stages, cp.async wait_group 2.  8 warps 2Mx4N.
//   EPI_POS: fused bias + bilinear pos-embed add (patch embed only).
// ---------------------------------------------------------------------------
#define EPI_BIAS      1
#define EPI_BIAS_GELU 2
#define EPI_BIAS_RES  3
#define EPI_POS       4

#define G4_AST  20
#define G4_BST  68
#define G4_BOFF 2560
#define G4_STG  4736
#define G4_NSTG 4
#define G4_SMEM (G4_NSTG * G4_STG * 4)

template<int EPI, bool OUTH>
__global__ void __launch_bounds__(256, 2)
gemm3(const __half* __restrict__ A, int lda,
      const __half* __restrict__ B, int ldb,
      void* __restrict__ Cv, int ldc,
      const float* __restrict__ bias,
      const float* __restrict__ Res, int ldr,
      int Md, int Nd, int Kd,
      const float* __restrict__ ptab)
{
    extern __shared__ uint32_t smbuf[];

    const int tid  = threadIdx.x;
    const int brow = blockIdx.y * 128;
    const int bcol = blockIdx.x * 128;
    const int w    = tid >> 5;
    const int lane = tid & 31;
    const int g    = lane >> 2;
    const int q    = lane & 3;
    const int wm   = w & 1;
    const int wn   = w >> 1;

    uint32_t smbase = (uint32_t)__cvta_generic_to_shared(smbuf);

    int aok[2], ak8[2];
    uint32_t sa[2];
    const __half* ga[2];
#pragma unroll
    for (int i = 0; i < 2; i++) {
        int c = tid + i * 256;
        int row = c >> 2;
        ak8[i] = (c & 3) * 8;
        aok[i] = (brow + row) < Md;
        sa[i] = smbase + (uint32_t)(row * G4_AST + (c & 3) * 4) * 4;
        ga[i] = A + (long long)(brow + row) * lda + ak8[i];
    }
    int bkr[2], bok[2];
    uint32_t sb[2];
    const __half* gb[2];
#pragma unroll
    for (int i = 0; i < 2; i++) {
        int c = tid + i * 256;
        bkr[i] = c >> 4;
        int n8 = (c & 15) * 8;
        bok[i] = (bcol + n8) < Nd;
        sb[i] = smbase + (uint32_t)(G4_BOFF + bkr[i] * G4_BST + (c & 15) * 4) * 4;
        gb[i] = B + (long long)bkr[i] * ldb + bcol + n8;
    }

    float acc[4][4][4];
#pragma unroll
    for (int i = 0; i < 4; i++)
#pragma unroll
        for (int j = 0; j < 4; j++)
#pragma unroll
            for (int r = 0; r < 4; r++) acc[i][j][r] = 0.f;

    const int ntk = (Kd + 31) >> 5;

    auto load_stage = [&](int k0, int st) {
        uint32_t off = (uint32_t)(st * G4_STG) * 4;
#pragma unroll
        for (int i = 0; i < 2; i++) {
            int va = (aok[i] && (k0 + ak8[i]) < Kd) ? 16 : 0;
            asm volatile("cp.async.cg.shared.global [%0], [%1], 16, %2;"
                         :: "r"(sa[i] + off), "l"(ga[i] + k0), "r"(va));
        }
#pragma unroll
        for (int i = 0; i < 2; i++) {
            int vb = (bok[i] && (k0 + bkr[i]) < Kd) ? 16 : 0;
            asm volatile("cp.async.cg.shared.global [%0], [%1], 16, %2;"
                         :: "r"(sb[i] + off), "l"(gb[i] + (long long)k0 * ldb), "r"(vb));
        }
    };

    load_stage(0, 0);
    asm volatile("cp.async.commit_group;");
    if (ntk > 1) load_stage(32, 1);
    asm volatile("cp.async.commit_group;");
    if (ntk > 2) load_stage(64, 2);
    asm volatile("cp.async.commit_group;");

    const int a_row = wm * 64 + (lane & 15);
    const uint32_t abase = smbase + (uint32_t)(a_row * G4_AST + (lane >> 4) * 4) * 4;
    const uint32_t bbase = smbase + (uint32_t)G4_BOFF * 4 +
        (uint32_t)((lane & 15) * G4_BST * 4 + (wn * 32 + (lane >> 4) * 8) * 2);

    for (int kt = 0; kt < ntk; kt++) {
        asm volatile("cp.async.wait_group 2;");
        __syncthreads();
        uint32_t soff = (uint32_t)((kt & 3) * G4_STG) * 4;

#pragma unroll
        for (int kg = 0; kg < 2; kg++) {
            uint32_t akg = soff + (uint32_t)(kg * 8) * 4;
            uint32_t bkg = soff + (uint32_t)(kg * 16 * G4_BST) * 4;

            uint32_t af[4][4], bf[2][4];
#pragma unroll
            for (int mt = 0; mt < 4; mt++)
                asm volatile("ldmatrix.sync.aligned.m8n8.x4.shared.b16 {%0,%1,%2,%3}, [%4];"
                             : "=r"(af[mt][0]), "=r"(af[mt][1]), "=r"(af[mt][2]), "=r"(af[mt][3])
                             : "r"(abase + akg + (uint32_t)(mt * 16 * G4_AST) * 4));
#pragma unroll
            for (int ng = 0; ng < 2; ng++)
                asm volatile("ldmatrix.sync.aligned.m8n8.x4.trans.shared.b16 {%0,%1,%2,%3}, [%4];"
                             : "=r"(bf[ng][0]), "=r"(bf[ng][1]), "=r"(bf[ng][2]), "=r"(bf[ng][3])
                             : "r"(bbase + bkg + (uint32_t)(ng * 32)));

#pragma unroll
            for (int mt = 0; mt < 4; mt++)
#pragma unroll
                for (int j = 0; j < 4; j++)
                    mma_f16(acc[mt][j],
                            af[mt][0], af[mt][1], af[mt][2], af[mt][3],
                            bf[j >> 1][(j & 1) * 2], bf[j >> 1][(j & 1) * 2 + 1]);
        }

        int ktn = kt + 3;
        if (ktn < ntk)
            load_stage(ktn * 32, ktn & 3);
        asm volatile("cp.async.commit_group;");
    }

    float*  Cf = (float*)Cv;
    __half* Ch = (__half*)Cv;
#pragma unroll
    for (int mt = 0; mt < 4; mt++) {
#pragma unroll
        for (int hh = 0; hh < 2; hh++) {
            int r = brow + wm * 64 + mt * 16 + g + 8 * hh;
            if (r >= Md) continue;

            // per-row bilerp setup for EPI_POS
            const float *p00 = nullptr, *p01 = nullptr, *p10 = nullptr, *p11 = nullptr;
            float w00, w01, w10, w11;
            if (EPI == EPI_POS) {
                int prow, pcol, ih, iw;
                token_pos(r, prow, pcol, ih, iw);
                int hd = ih - 1, wd = iw - 1;
                int hnum = 47 * prow, wnum = 47 * pcol;
                int hf = hnum / hd, wf = wnum / wd;
                float dh = (float)(hnum - hf * hd) / (float)hd;
                float dw = (float)(wnum - wf * wd) / (float)wd;
                int hc = min(hf + 1, 47), wc = min(wf + 1, 47);
                w00 = (1.f - dh) * (1.f - dw);
                w01 = (1.f - dh) * dw;
                w10 = dh * (1.f - dw);
                w11 = dh * dw;
                p00 = ptab + (size_t)(hf * 48 + wf) * DMODEL;
                p01 = ptab + (size_t)(hf * 48 + wc) * DMODEL;
                p10 = ptab + (size_t)(hc * 48 + wf) * DMODEL;
                p11 = ptab + (size_t)(hc * 48 + wc) * DMODEL;
            }

#pragma unroll
            for (int j = 0; j < 4; j++) {
                int c = bcol + wn * 32 + j * 8 + 2 * q;
                if (c >= Nd) continue;
                float v0 = acc[mt][j][hh * 2];
                float v1 = acc[mt][j][hh * 2 + 1];
                v0 += bias[c]; v1 += bias[c + 1];
                if (EPI == EPI_BIAS_GELU) { v0 = gelu_tanh(v0); v1 = gelu_tanh(v1); }
                if (EPI == EPI_BIAS_RES)  {
                    v0 += Res[(long long)r * ldr + c];
                    v1 += Res[(long long)r * ldr + c + 1];
                }
                if (EPI == EPI_POS) {
                    v0 += p00[c] * w00 + p01[c] * w01 + p10[c] * w10 + p11[c] * w11;
                    v1 += p00[c + 1] * w00 + p01[c + 1] * w01 +
                          p10[c + 1] * w10 + p11[c + 1] * w11;
                }
                if (OUTH) {
                    __half2 hv = __floats2half2_rn(v0, v1);
                    *reinterpret_cast<__half2*>(Ch + (long long)r * ldc + c) = hv;
                } else {
                    *reinterpret_cast<float2*>(Cf + (long long)r * ldc + c) = make_float2(v0, v1);
                }
            }
        }
    }
}

// ---------------------------------------------------------------------------
// Fused flash attention v2 (unchanged — verified).
// ---------------------------------------------------------------------------
#define FROW 44

__global__ void __launch_bounds__(256, 2)
flash_h(const __half* __restrict__ qkv, __half* __restrict__ attn)
{
    __shared__ uint32_t Qs[128 * FROW];
    __shared__ uint32_t Ks[64 * FROW];
    __shared__ uint32_t Vs[64 * FROW];

    int t = blockIdx.x;
    int head = blockIdx.y;
    int st, S, q0;
    if (t < 18)      { st = 0;    S = 2304; q0 = t * 128; }
    else if (t < 34) { st = 2304; S = 2048; q0 = (t - 18) * 128; }
    else if (t < 42) { st = 4352; S = 960;  q0 = (t - 34) * 128; }
    else             { st = 5312; S = 960;  q0 = (t - 42) * 128; }

    const int tid  = threadIdx.x;
    const int w    = tid >> 5;
    const int lane = tid & 31;
    const int g    = lane >> 2;
    const int q    = lane & 3;
    const int rowbase = w * 16;

    const float scale = 0.11785113019775793f;

    for (int s = tid; s < 128 * 9; s += 256) {
        int row = s / 9, c = s % 9;
        uint4 v = make_uint4(0, 0, 0, 0);
        if (q0 + row < S)
            v = *reinterpret_cast<const uint4*>(
                qkv + (size_t)(st + q0 + row) * QKVW + head * HDIM + c * 8);
        *reinterpret_cast<uint4*>(&Qs[row * FROW + c * 4]) = v;
    }
    for (int s = tid; s < 128 * 8; s += 256) Qs[(s >> 3) * FROW + 36 + (s & 7)] = 0;
    for (int s = tid; s < 64 * 8; s += 256) {
        Ks[(s >> 3) * FROW + 36 + (s & 7)] = 0;
        Vs[(s >> 3) * FROW + 36 + (s & 7)] = 0;
    }

    float m0 = -1e30f, m1 = -1e30f, l0 = 0.f, l1 = 0.f;
    float O[10][4];
#pragma unroll
    for (int i = 0; i < 10; i++)
#pragma unroll
        for (int r = 0; r < 4; r++) O[i][r] = 0.f;

    uint32_t smQ = (uint32_t)__cvta_generic_to_shared(Qs);
    uint32_t smK = (uint32_t)__cvta_generic_to_shared(Ks);
    uint32_t smV = (uint32_t)__cvta_generic_to_shared(Vs);
    const uint32_t qsb = smQ + (uint32_t)((rowbase + (lane & 15)) * FROW + (lane >> 4) * 4) * 4;
    const uint32_t ksb = smK + (uint32_t)((((lane & 7) + ((lane >> 4) << 3)) * FROW) +
                                          ((lane >> 3) & 1) * 4) * 4;
    const uint32_t vsb = smV + (uint32_t)(((lane & 15) * FROW) + (lane >> 4) * 4) * 4;

    const int nkv = S >> 6;
    for (int j = 0; j < nkv; j++) {
        __syncthreads();
        const int kv0 = j * 64;
        for (int s = tid; s < 64 * 9; s += 256) {
            int row = s / 9, c = s % 9;
            *reinterpret_cast<uint4*>(&Ks[row * FROW + c * 4]) =
                *reinterpret_cast<const uint4*>(
                    qkv + (size_t)(st + kv0 + row) * QKVW + DMODEL + head * HDIM + c * 8);
        }
        for (int s = tid; s < 64 * 9; s += 256) {
            int row = s / 9, c = s % 9;
            *reinterpret_cast<uint4*>(&Vs[row * FROW + c * 4]) =
                *reinterpret_cast<const uint4*>(
                    qkv + (size_t)(st + kv0 + row) * QKVW + 2 * DMODEL + head * HDIM + c * 8);
        }
        __syncthreads();

        float acc[8][4];
#pragma unroll
        for (int i = 0; i < 8; i++)
#pragma unroll
            for (int r = 0; r < 4; r++) acc[i][r] = 0.f;

#pragma unroll
        for (int kb = 0; kb < 5; kb++) {
            uint32_t af[4];
            asm volatile("ldmatrix.sync.aligned.m8n8.x4.shared.b16 {%0,%1,%2,%3}, [%4];"
                         : "=r"(af[0]), "=r"(af[1]), "=r"(af[2]), "=r"(af[3])
                         : "r"(qsb + (uint32_t)(kb * 8) * 4));
#pragma unroll
            for (int nt4 = 0; nt4 < 4; nt4++) {
                uint32_t bf[4];
                asm volatile("ldmatrix.sync.aligned.m8n8.x4.shared.b16 {%0,%1,%2,%3}, [%4];"
                             : "=r"(bf[0]), "=r"(bf[1]), "=r"(bf[2]), "=r"(bf[3])
                             : "r"(ksb + (uint32_t)(nt4 * 16 * FROW + kb * 8) * 4));
                mma_f16(acc[2 * nt4    ], af[0], af[1], af[2], af[3], bf[0], bf[1]);
                mma_f16(acc[2 * nt4 + 1], af[0], af[1], af[2], af[3], bf[2], bf[3]);
            }
        }
#pragma unroll
        for (int i = 0; i < 8; i++)
#pragma unroll
            for (int r = 0; r < 4; r++) acc[i][r] *= scale;

        float mx0 = -1e30f, mx1 = -1e30f;
#pragma unroll
        for (int i = 0; i < 8; i++) {
            mx0 = fmaxf(mx0, fmaxf(acc[i][0], acc[i][1]));
            mx1 = fmaxf(mx1, fmaxf(acc[i][2], acc[i][3]));
        }
        mx0 = fmaxf(mx0, __shfl_xor_sync(0xffffffffu, mx0, 1));
        mx0 = fmaxf(mx0, __shfl_xor_sync(0xffffffffu, mx0, 2));
        mx1 = fmaxf(mx1, __shfl_xor_sync(0xffffffffu, mx1, 1));
        mx1 = fmaxf(mx1, __shfl_xor_sync(0xffffffffu, mx1, 2));
        float mn0 = fmaxf(m0, mx0), mn1 = fmaxf(m1, mx1);
        float al0 = __expf(m0 - mn0), al1 = __expf(m1 - mn1);
        m0 = mn0; m1 = mn1;

        float rs0 = 0.f, rs1 = 0.f;
#pragma unroll
        for (int i = 0; i < 8; i++) {
            acc[i][0] = __expf(acc[i][0] - mn0);
            acc[i][1] = __expf(acc[i][1] - mn0);
            acc[i][2] = __expf(acc[i][2] - mn1);
            acc[i][3] = __expf(acc[i][3] - mn1);
            rs0 += acc[i][0] + acc[i][1];
            rs1 += acc[i][2] + acc[i][3];
        }
        rs0 += __shfl_xor_sync(0xffffffffu, rs0, 1);
        rs0 += __shfl_xor_sync(0xffffffffu, rs0, 2);
        rs1 += __shfl_xor_sync(0xffffffffu, rs1, 1);
        rs1 += __shfl_xor_sync(0xffffffffu, rs1, 2);
        l0 = l0 * al0 + rs0;
        l1 = l1 * al1 + rs1;

#pragma unroll
        for (int i = 0; i < 10; i++) {
            O[i][0] *= al0; O[i][1] *= al0;
            O[i][2] *= al1; O[i][3] *= al1;
        }

        uint32_t pa[4][4];
#pragma unroll
        for (int kb = 0; kb < 4; kb++) {
            pa[kb][0] = pack_h2(acc[2 * kb][0],     acc[2 * kb][1]);
            pa[kb][1] = pack_h2(acc[2 * kb][2],     acc[2 * kb][3]);
            pa[kb][2] = pack_h2(acc[2 * kb + 1][0], acc[2 * kb + 1][1]);
            pa[kb][3] = pack_h2(acc[2 * kb + 1][2], acc[2 * kb + 1][3]);
        }

#pragma unroll
        for (int kb = 0; kb < 4; kb++) {
#pragma unroll
            for (int vt = 0; vt < 5; vt++) {
                uint32_t bf[4];
                asm volatile("ldmatrix.sync.aligned.m8n8.x4.trans.shared.b16 {%0,%1,%2,%3}, [%4];"
                             : "=r"(bf[0]), "=r"(bf[1]), "=r"(bf[2]), "=r"(bf[3])
                             : "r"(vsb + (uint32_t)(kb * 16 * FROW + vt * 8) * 4));
                mma_f16(O[2 * vt    ], pa[kb][0], pa[kb][1], pa[kb][2], pa[kb][3], bf[0], bf[1]);
                mma_f16(O[2 * vt + 1], pa[kb][0], pa[kb][1], pa[kb][2], pa[kb][3], bf[2], bf[3]);
            }
        }
    }

#pragma unroll
    for (int h = 0; h < 2; h++) {
        int r = rowbase + g + 8 * h;
        if (q0 + r >= S) continue;
        float inv = 1.0f / (h == 0 ? l0 : l1);
#pragma unroll
        for (int ntl = 0; ntl < 9; ntl++) {
            int c = ntl * 8 + 2 * q;
            __half2 hv = __floats2half2_rn(O[ntl][2 * h] * inv, O[ntl][2 * h + 1] * inv);
            *reinterpret_cast<__half2*>(
                attn + (size_t)(st + q0 + r) * DMODEL + head * HDIM + c) = hv;
        }
    }
}

// ---------------------------------------------------------------------------
// Host launcher
// ---------------------------------------------------------------------------
#define SYMF(p, s) do { void* _t; cudaGetSymbolAddress(&_t, s); p = (float*)_t; } while (0)
#define SYMH(p, s) do { void* _t; cudaGetSymbolAddress(&_t, s); p = (__half*)_t; } while (0)

static inline dim3 ggrid3(int Md, int Nd) {
    return dim3((Nd + 127) / 128, (Md + 127) / 128);
}

extern "C" void kernel_launch(void* const* d_in, const int* in_sizes, int n_in,
                              void* d_out, int out_size)
{
    (void)in_sizes; (void)n_in; (void)out_size;
    const float* pixel    = (const float*)d_in[0];
    const float* patch_w  = (const float*)d_in[2];
    const float* patch_b  = (const float*)d_in[3];
    const float* pos_tab  = (const float*)d_in[4];
    const float* ln1_s    = (const float*)d_in[5];
    const float* ln1_b    = (const float*)d_in[6];
    const float* qkv_w    = (const float*)d_in[7];
    const float* qkv_b    = (const float*)d_in[8];
    const float* proj_w   = (const float*)d_in[9];
    const float* proj_b   = (const float*)d_in[10];
    const float* ln2_s    = (const float*)d_in[11];
    const float* ln2_b    = (const float*)d_in[12];
    const float* fc1_w    = (const float*)d_in[13];
    const float* fc1_b    = (const float*)d_in[14];
    const float* fc2_w    = (const float*)d_in[15];
    const float* fc2_b    = (const float*)d_in[16];
    const float* m_ln_s   = (const float*)d_in[17];
    const float* m_ln_b   = (const float*)d_in[18];
    const float* m_fc1_w  = (const float*)d_in[19];
    const float* m_fc1_b  = (const float*)d_in[20];
    const float* m_fc2_w  = (const float*)d_in[21];
    const float* m_fc2_b  = (const float*)d_in[22];
    float* out = (float*)d_out;

    float *x;
    __half *pix, *hh, *qkvh, *attnh, *mlph, *wt;
    SYMF(x, g_x);
    SYMH(pix, g_pix); SYMH(hh, g_hh); SYMH(qkvh, g_qkvh);
    SYMH(attnh, g_attnh); SYMH(mlph, g_mlph); SYMH(wt, g_wt);

    static bool attr_set = false;
    if (!attr_set) {
        cudaFuncSetAttribute(gemm3<EPI_BIAS, false>,
                             cudaFuncAttributeMaxDynamicSharedMemorySize, G4_SMEM);
        cudaFuncSetAttribute(gemm3<EPI_BIAS, true>,
                             cudaFuncAttributeMaxDynamicSharedMemorySize, G4_SMEM);
        cudaFuncSetAttribute(gemm3<EPI_BIAS_GELU, true>,
                             cudaFuncAttributeMaxDynamicSharedMemorySize, G4_SMEM);
        cudaFuncSetAttribute(gemm3<EPI_BIAS_RES, false>,
                             cudaFuncAttributeMaxDynamicSharedMemorySize, G4_SMEM);
        cudaFuncSetAttribute(gemm3<EPI_POS, false>,
                             cudaFuncAttributeMaxDynamicSharedMemorySize, G4_SMEM);
        attr_set = true;
    }

    // ---- fused fp32->fp16 conversion (single launch, all streams)
    {
        ConvJobs J;
        const float* srcs[NSEG] = {
            pixel, patch_w,
            qkv_w,  qkv_w  + SZ_QKV,
            proj_w, proj_w + SZ_PROJ,
            fc1_w,  fc1_w  + SZ_FC1,
            fc2_w,  fc2_w  + SZ_FC2,
            m_fc1_w, m_fc2_w, nullptr };
        __half* dsts[NSEG] = {
            pix, wt + OFF_PATCH,
            wt + OFF_QKV,  wt + OFF_QKV + SZ_QKV,
            wt + OFF_PROJ, wt + OFF_PROJ + SZ_PROJ,
            wt + OFF_FC1,  wt + OFF_FC1 + SZ_FC1,
            wt + OFF_FC2,  wt + OFF_FC2 + SZ_FC2,
            wt + OFF_MFC1, wt + OFF_MFC2, nullptr };
        long long sizes[NSEG] = {
            (long long)NTOK * CIN, (long long)SZ_PATCH,
            (long long)SZ_QKV, (long long)SZ_QKV,
            (long long)SZ_PROJ, (long long)SZ_PROJ,
            (long long)SZ_FC1, (long long)SZ_FC1,
            (long long)SZ_FC2, (long long)SZ_FC2,
            (long long)SZ_MFC1, (long long)SZ_MFC2, 0 };
        srcs[12]  = m_fc2_w;
        dsts[12]  = wt + OFF_MFC2;
        int off = 0;
        for (int s = 0; s < NSEG; s++) {
            J.src[s] = (const float4*)srcs[s];
            J.dst[s] = (uint2*)dsts[s];
            J.off[s] = off;
            off += (int)(sizes[s] / 4);
        }
        J.off[NSEG] = off;
        convall<<<(off + 255) / 256, 256>>>(J, off);
    }

    cossin_kernel<<<(NTOK * 36 + 255) / 256, 256>>>();

    // Patch embed + bias + pos-embed -> x (fp32) in one kernel
    gemm3<EPI_POS, false><<<ggrid3(NTOK, DMODEL), 256, G4_SMEM>>>(
        pix, CIN, wt + OFF_PATCH, DMODEL, x, DMODEL,
        patch_b, nullptr, 0, NTOK, DMODEL, CIN, pos_tab);

    for (int l = 0; l < 2; l++) {
        ln_h<<<NTOK, 288>>>(x, hh, ln1_s + l * DMODEL, ln1_b + l * DMODEL);

        gemm3<EPI_BIAS, true><<<ggrid3(NTOK, QKVW), 256, G4_SMEM>>>(
            hh, DMODEL, wt + OFF_QKV + l * SZ_QKV, QKVW, qkvh, QKVW,
            qkv_b + (size_t)l * QKVW, nullptr, 0, NTOK, QKVW, DMODEL, nullptr);

        rope_h<<<NTOK, 576>>>();

        flash_h<<<dim3(50, HEADS), 256>>>(qkvh, attnh);

        gemm3<EPI_BIAS_RES, false><<<ggrid3(NTOK, DMODEL), 256, G4_SMEM>>>(
            attnh, DMODEL, wt + OFF_PROJ + l * SZ_PROJ, DMODEL, x, DMODEL,
            proj_b + (size_t)l * DMODEL, x, DMODEL, NTOK, DMODEL, DMODEL, nullptr);

        ln_h<<<NTOK, 288>>>(x, hh, ln2_s + l * DMODEL, ln2_b + l * DMODEL);

        gemm3<EPI_BIAS_GELU, true><<<ggrid3(NTOK, IDIM), 256, G4_SMEM>>>(
            hh, DMODEL, wt + OFF_FC1 + l * SZ_FC1, IDIM, mlph, IDIM,
            fc1_b + (size_t)l * IDIM, nullptr, 0, NTOK, IDIM, DMODEL, nullptr);

        gemm3<EPI_BIAS_RES, false><<<ggrid3(NTOK, DMODEL), 256, G4_SMEM>>>(
            mlph, IDIM, wt + OFF_FC2 + l * SZ_FC2, DMODEL, x, DMODEL,
            fc2_b + (size_t)l * DMODEL, x, DMODEL, NTOK, DMODEL, IDIM, nullptr);
    }

    // merger
    ln_h<<<NTOK, 288>>>(x, hh, m_ln_s, m_ln_b);   // hh viewed as [1568][4608]

    gemm3<EPI_BIAS_GELU, true><<<ggrid3(MROWS, MD4), 256, G4_SMEM>>>(
        hh, MD4, wt + OFF_MFC1, MD4, mlph, MD4,
        m_fc1_b, nullptr, 0, MROWS, MD4, MD4, nullptr);

    gemm3<EPI_BIAS, false><<<ggrid3(MROWS, DOUT), 256, G4_SMEM>>>(
        mlph, MD4, wt + OFF_MFC2, DOUT, out, DOUT,
        m_fc2_b, nullptr, 0, MROWS, DOUT, MD4, nullptr);
}

// round 16
// speedup vs baseline: 1.0041x; 1.0041x over previous
#include <cuda_runtime.h>
#include <cuda_fp16.h>
#include <math.h>
#include <stdint.h>

// ---------------------------------------------------------------------------
// Problem constants (GRID fixed: [[1,48,48],[1,32,64],[2,24,40]])
// ---------------------------------------------------------------------------
#define NTOK    6272
#define DMODEL  1152
#define HEADS   16
#define HDIM    72
#define IDIM    4304
#define DOUT    2048
#define MROWS   1568
#define MD4     4608
#define QKVW    3456
#define CIN     1536

// ---------------------------------------------------------------------------
// Scratch buffers
// ---------------------------------------------------------------------------
__device__ float  g_x    [NTOK * DMODEL];        // residual (fp32)
__device__ __half g_pix  [NTOK * CIN];           // pixel fp16
__device__ __half g_hh   [NTOK * DMODEL];        // LN out fp16
__device__ __half g_qkvh [NTOK * QKVW];          // qkv fp16
__device__ __half g_attnh[NTOK * DMODEL];        // attn out fp16
__device__ __half g_mlph [NTOK * IDIM];          // mlp hidden fp16

// fp16 weights, natural [K,N] layout (no transpose)
#define SZ_PATCH (1536ULL * 1152)
#define SZ_QKV   (1152ULL * 3456)
#define SZ_PROJ  (1152ULL * 1152)
#define SZ_FC1   (1152ULL * 4304)
#define SZ_FC2   (4304ULL * 1152)
#define SZ_MFC1  (4608ULL * 4608)
#define SZ_MFC2  (4608ULL * 2048)
#define OFF_PATCH 0ULL
#define OFF_QKV   (OFF_PATCH + SZ_PATCH)
#define OFF_PROJ  (OFF_QKV + 2 * SZ_QKV)
#define OFF_FC1   (OFF_PROJ + 2 * SZ_PROJ)
#define OFF_FC2   (OFF_FC1 + 2 * SZ_FC1)
#define OFF_MFC1  (OFF_FC2 + 2 * SZ_FC2)
#define OFF_MFC2  (OFF_MFC1 + SZ_MFC1)
#define WT_TOTAL  (OFF_MFC2 + SZ_MFC2)
__device__ __half g_wt[WT_TOTAL];

// ---------------------------------------------------------------------------
__device__ __forceinline__ void token_pos(int n, int& row, int& col, int& ih, int& iw)
{
    int local, h, w;
    if (n < 2304)      { local = n;          h = 48; w = 48; }
    else if (n < 4352) { local = n - 2304;   h = 32; w = 64; }
    else               { local = n - 4352;   h = 24; w = 40; }
    int rem = local % (h * w);
    int wb_cnt = w >> 1;
    int blk = rem >> 2, within = rem & 3;
    int hb = blk / wb_cnt, wb = blk % wb_cnt;
    row = hb * 2 + (within >> 1);
    col = wb * 2 + (within & 1);
    ih = h; iw = w;
}

// ---------------------------------------------------------------------------
// Fused fp32->fp16 convert for ALL prep streams in one launch.
// ---------------------------------------------------------------------------
#define NSEG 13
struct ConvJobs {
    const float4* src[NSEG];
    uint2*        dst[NSEG];
    int           off[NSEG + 1];
};

__global__ void convall(ConvJobs J, int total)
{
    int i = blockIdx.x * blockDim.x + threadIdx.x;
    if (i >= total) return;
    int s = 0;
#pragma unroll
    for (int k = 1; k < NSEG; k++) s += (i >= J.off[k]) ? 1 : 0;
    int local = i - J.off[s];
    float4 v = J.src[s][local];
    __half2 lo = __floats2half2_rn(v.x, v.y);
    __half2 hi = __floats2half2_rn(v.z, v.w);
    J.dst[s][local] =
        make_uint2(*reinterpret_cast<uint32_t*>(&lo), *reinterpret_cast<uint32_t*>(&hi));
}

__device__ __forceinline__ float warp_sum(float v)
{
#pragma unroll
    for (int o = 16; o > 0; o >>= 1) v += __shfl_xor_sync(0xffffffffu, v, o);
    return v;
}

// LayerNorm fp32 in -> fp16 out; single-pass (sum + sumsq together)
__global__ void ln_h(const float* __restrict__ in, __half* __restrict__ out,
                     const float* __restrict__ s, const float* __restrict__ b)
{
    __shared__ float sh[9], sh2[9];
    __shared__ float stat[2];
    int n = blockIdx.x;
    const float4* xr4 = reinterpret_cast<const float4*>(in + (size_t)n * DMODEL);
    int t = threadIdx.x, wid = t >> 5, lane = t & 31;

    float4 v = xr4[t];
    float lsum = v.x + v.y + v.z + v.w;
    float lsq  = v.x * v.x + v.y * v.y + v.z * v.z + v.w * v.w;
    float ws = warp_sum(lsum);
    float wq = warp_sum(lsq);
    if (lane == 0) { sh[wid] = ws; sh2[wid] = wq; }
    __syncthreads();
    if (t == 0) {
        float tot = 0.f, totq = 0.f;
#pragma unroll
        for (int i = 0; i < 9; i++) { tot += sh[i]; totq += sh2[i]; }
        float mu = tot * (1.0f / DMODEL);
        float var = totq * (1.0f / DMODEL) - mu * mu;
        stat[0] = mu;
        stat[1] = rsqrtf(var + 1e-6f);
    }
    __syncthreads();
    float mu = stat[0], r = stat[1];
    float4 s4 = reinterpret_cast<const float4*>(s)[t];
    float4 b4 = reinterpret_cast<const float4*>(b)[t];
    __half2 p0 = __floats2half2_rn((v.x - mu) * r * s4.x + b4.x,
                                   (v.y - mu) * r * s4.y + b4.y);
    __half2 p1 = __floats2half2_rn((v.z - mu) * r * s4.z + b4.z,
                                   (v.w - mu) * r * s4.w + b4.w);
    reinterpret_cast<uint2*>(out + (size_t)n * DMODEL)[t] =
        make_uint2(*reinterpret_cast<uint32_t*>(&p0), *reinterpret_cast<uint32_t*>(&p1));
}

// RoPE in-place on fp16 qkv, cos/sin computed in-kernel (smem broadcast)
__global__ void rope2()
{
    __shared__ float cs[36], sn[36];
    int n = blockIdx.x;
    int t = threadIdx.x;
    if (t < 36) {
        int row, col, ih, iw;
        token_pos(n, row, col, ih, iw);
        int j = (t < 18) ? t : t - 18;
        float p = (t < 18) ? (float)row : (float)col;
        float inv = __expf(-(float)j * 0.5117865387079628f);   // 10000^{-j/18}
        float ang = p * inv;
        cs[t] = cosf(ang);
        sn[t] = sinf(ang);
    }
    __syncthreads();
    int h = t / 36, d = t % 36;
    float c = cs[d], s = sn[d];
    __half* q = g_qkvh + (size_t)n * QKVW + h * HDIM;
    __half* k = q + DMODEL;
    float q0 = __half2float(q[d]), q1 = __half2float(q[d + 36]);
    q[d]      = __float2half_rn(q0 * c - q1 * s);
    q[d + 36] = __float2half_rn(q1 * c + q0 * s);
    float k0 = __half2float(k[d]), k1 = __half2float(k[d + 36]);
    k[d]      = __float2half_rn(k0 * c - k1 * s);
    k[d + 36] = __float2half_rn(k1 * c + k0 * s);
}

// ---------------------------------------------------------------------------
// mma / misc helpers
// ---------------------------------------------------------------------------
__device__ __forceinline__ void mma_f16(float c[4],
                                        uint32_t a0, uint32_t a1, uint32_t a2, uint32_t a3,
                                        uint32_t b0, uint32_t b1)
{
    asm volatile(
        "mma.sync.aligned.m16n8k16.row.col.f32.f16.f16.f32 "
        "{%0,%1,%2,%3}, {%4,%5,%6,%7}, {%8,%9}, {%0,%1,%2,%3};\n"
        : "+f"(c[0]), "+f"(c[1]), "+f"(c[2]), "+f"(c[3])
        : "r"(a0), "r"(a1), "r"(a2), "r"(a3), "r"(b0), "r"(b1));
}

// fast gelu: HW tanh approx (MUFU.TANH)
__device__ __forceinline__ float gelu_tanh(float x)
{
    float u = 0.7978845608028654f * (x + 0.044715f * x * x * x);
    float t;
    asm("tanh.approx.f32 %0, %1;" : "=f"(t) : "f"(u));
    return 0.5f * x * (1.f + t);
}

__device__ __forceinline__ uint32_t pack_h2(float lo, float hi)
{
    __half2 h = __floats2half2_rn(lo, hi);
    return *reinterpret_cast<uint32_t*>(&h);
}

// ---------------------------------------------------------------------------
// GEMM v4: A fp16 [M,K] row-major, B fp16 [K,N] row-major, C fp32 or fp16.
//   Block 128x128, BK=32, 4 stages, cp.async wait_group 2.  8 warps 2Mx4N.
//   EPI_POS: fused bias + bilinear pos-embed add (patch embed only).
// ---------------------------------------------------------------------------
#define EPI_BIAS      1
#define EPI_BIAS_GELU 2
#define EPI_BIAS_RES  3
#define EPI_POS       4

#define G4_AST  20
#define G4_BST  68
#define G4_BOFF 2560
#define G4_STG  4736
#define G4_NSTG 4
#define G4_SMEM (G4_NSTG * G4_STG * 4)

template<int EPI, bool OUTH>
__global__ void __launch_bounds__(256, 2)
gemm3(const __half* __restrict__ A, int lda,
      const __half* __restrict__ B, int ldb,
      void* __restrict__ Cv, int ldc,
      const float* __restrict__ bias,
      const float* __restrict__ Res, int ldr,
      int Md, int Nd, int Kd,
      const float* __restrict__ ptab)
{
    extern __shared__ uint32_t smbuf[];

    const int tid  = threadIdx.x;
    const int brow = blockIdx.y * 128;
    const int bcol = blockIdx.x * 128;
    const int w    = tid >> 5;
    const int lane = tid & 31;
    const int g    = lane >> 2;
    const int q    = lane & 3;
    const int wm   = w & 1;
    const int wn   = w >> 1;

    uint32_t smbase = (uint32_t)__cvta_generic_to_shared(smbuf);

    int aok[2], ak8[2];
    uint32_t sa[2];
    const __half* ga[2];
#pragma unroll
    for (int i = 0; i < 2; i++) {
        int c = tid + i * 256;
        int row = c >> 2;
        ak8[i] = (c & 3) * 8;
        aok[i] = (brow + row) < Md;
        sa[i] = smbase + (uint32_t)(row * G4_AST + (c & 3) * 4) * 4;
        ga[i] = A + (long long)(brow + row) * lda + ak8[i];
    }
    int bkr[2], bok[2];
    uint32_t sb[2];
    const __half* gb[2];
#pragma unroll
    for (int i = 0; i < 2; i++) {
        int c = tid + i * 256;
        bkr[i] = c >> 4;
        int n8 = (c & 15) * 8;
        bok[i] = (bcol + n8) < Nd;
        sb[i] = smbase + (uint32_t)(G4_BOFF + bkr[i] * G4_BST + (c & 15) * 4) * 4;
        gb[i] = B + (long long)bkr[i] * ldb + bcol + n8;
    }

    float acc[4][4][4];
#pragma unroll
    for (int i = 0; i < 4; i++)
#pragma unroll
        for (int j = 0; j < 4; j++)
#pragma unroll
            for (int r = 0; r < 4; r++) acc[i][j][r] = 0.f;

    const int ntk = (Kd + 31) >> 5;

    auto load_stage = [&](int k0, int st) {
        uint32_t off = (uint32_t)(st * G4_STG) * 4;
#pragma unroll
        for (int i = 0; i < 2; i++) {
            int va = (aok[i] && (k0 + ak8[i]) < Kd) ? 16 : 0;
            asm volatile("cp.async.cg.shared.global [%0], [%1], 16, %2;"
                         :: "r"(sa[i] + off), "l"(ga[i] + k0), "r"(va));
        }
#pragma unroll
        for (int i = 0; i < 2; i++) {
            int vb = (bok[i] && (k0 + bkr[i]) < Kd) ? 16 : 0;
            asm volatile("cp.async.cg.shared.global [%0], [%1], 16, %2;"
                         :: "r"(sb[i] + off), "l"(gb[i] + (long long)k0 * ldb), "r"(vb));
        }
    };

    load_stage(0, 0);
    asm volatile("cp.async.commit_group;");
    if (ntk > 1) load_stage(32, 1);
    asm volatile("cp.async.commit_group;");
    if (ntk > 2) load_stage(64, 2);
    asm volatile("cp.async.commit_group;");

    const int a_row = wm * 64 + (lane & 15);
    const uint32_t abase = smbase + (uint32_t)(a_row * G4_AST + (lane >> 4) * 4) * 4;
    const uint32_t bbase = smbase + (uint32_t)G4_BOFF * 4 +
        (uint32_t)((lane & 15) * G4_BST * 4 + (wn * 32 + (lane >> 4) * 8) * 2);

    for (int kt = 0; kt < ntk; kt++) {
        asm volatile("cp.async.wait_group 2;");
        __syncthreads();
        uint32_t soff = (uint32_t)((kt & 3) * G4_STG) * 4;

#pragma unroll
        for (int kg = 0; kg < 2; kg++) {
            uint32_t akg = soff + (uint32_t)(kg * 8) * 4;
            uint32_t bkg = soff + (uint32_t)(kg * 16 * G4_BST) * 4;

            uint32_t af[4][4], bf[2][4];
#pragma unroll
            for (int mt = 0; mt < 4; mt++)
                asm volatile("ldmatrix.sync.aligned.m8n8.x4.shared.b16 {%0,%1,%2,%3}, [%4];"
                             : "=r"(af[mt][0]), "=r"(af[mt][1]), "=r"(af[mt][2]), "=r"(af[mt][3])
                             : "r"(abase + akg + (uint32_t)(mt * 16 * G4_AST) * 4));
#pragma unroll
            for (int ng = 0; ng < 2; ng++)
                asm volatile("ldmatrix.sync.aligned.m8n8.x4.trans.shared.b16 {%0,%1,%2,%3}, [%4];"
                             : "=r"(bf[ng][0]), "=r"(bf[ng][1]), "=r"(bf[ng][2]), "=r"(bf[ng][3])
                             : "r"(bbase + bkg + (uint32_t)(ng * 32)));

#pragma unroll
            for (int mt = 0; mt < 4; mt++)
#pragma unroll
                for (int j = 0; j < 4; j++)
                    mma_f16(acc[mt][j],
                            af[mt][0], af[mt][1], af[mt][2], af[mt][3],
                            bf[j >> 1][(j & 1) * 2], bf[j >> 1][(j & 1) * 2 + 1]);
        }

        int ktn = kt + 3;
        if (ktn < ntk)
            load_stage(ktn * 32, ktn & 3);
        asm volatile("cp.async.commit_group;");
    }

    float*  Cf = (float*)Cv;
    __half* Ch = (__half*)Cv;
#pragma unroll
    for (int mt = 0; mt < 4; mt++) {
#pragma unroll
        for (int hh = 0; hh < 2; hh++) {
            int r = brow + wm * 64 + mt * 16 + g + 8 * hh;
            if (r >= Md) continue;

            const float *p00 = nullptr, *p01 = nullptr, *p10 = nullptr, *p11 = nullptr;
            float w00, w01, w10, w11;
            if (EPI == EPI_POS) {
                int prow, pcol, ih, iw;
                token_pos(r, prow, pcol, ih, iw);
                int hd = ih - 1, wd = iw - 1;
                int hnum = 47 * prow, wnum = 47 * pcol;
                int hf = hnum / hd, wf = wnum / wd;
                float dh = (float)(hnum - hf * hd) / (float)hd;
                float dw = (float)(wnum - wf * wd) / (float)wd;
                int hc = min(hf + 1, 47), wc = min(wf + 1, 47);
                w00 = (1.f - dh) * (1.f - dw);
                w01 = (1.f - dh) * dw;
                w10 = dh * (1.f - dw);
                w11 = dh * dw;
                p00 = ptab + (size_t)(hf * 48 + wf) * DMODEL;
                p01 = ptab + (size_t)(hf * 48 + wc) * DMODEL;
                p10 = ptab + (size_t)(hc * 48 + wf) * DMODEL;
                p11 = ptab + (size_t)(hc * 48 + wc) * DMODEL;
            }

#pragma unroll
            for (int j = 0; j < 4; j++) {
                int c = bcol + wn * 32 + j * 8 + 2 * q;
                if (c >= Nd) continue;
                float v0 = acc[mt][j][hh * 2];
                float v1 = acc[mt][j][hh * 2 + 1];
                v0 += bias[c]; v1 += bias[c + 1];
                if (EPI == EPI_BIAS_GELU) { v0 = gelu_tanh(v0); v1 = gelu_tanh(v1); }
                if (EPI == EPI_BIAS_RES)  {
                    v0 += Res[(long long)r * ldr + c];
                    v1 += Res[(long long)r * ldr + c + 1];
                }
                if (EPI == EPI_POS) {
                    v0 += p00[c] * w00 + p01[c] * w01 + p10[c] * w10 + p11[c] * w11;
                    v1 += p00[c + 1] * w00 + p01[c + 1] * w01 +
                          p10[c + 1] * w10 + p11[c + 1] * w11;
                }
                if (OUTH) {
                    __half2 hv = __floats2half2_rn(v0, v1);
                    *reinterpret_cast<__half2*>(Ch + (long long)r * ldc + c) = hv;
                } else {
                    *reinterpret_cast<float2*>(Cf + (long long)r * ldc + c) = make_float2(v0, v1);
                }
            }
        }
    }
}

// ---------------------------------------------------------------------------
// Fused flash attention v2 (unchanged — verified).
// ---------------------------------------------------------------------------
#define FROW 44

__global__ void __launch_bounds__(256, 2)
flash_h(const __half* __restrict__ qkv, __half* __restrict__ attn)
{
    __shared__ uint32_t Qs[128 * FROW];
    __shared__ uint32_t Ks[64 * FROW];
    __shared__ uint32_t Vs[64 * FROW];

    int t = blockIdx.x;
    int head = blockIdx.y;
    int st, S, q0;
    if (t < 18)      { st = 0;    S = 2304; q0 = t * 128; }
    else if (t < 34) { st = 2304; S = 2048; q0 = (t - 18) * 128; }
    else if (t < 42) { st = 4352; S = 960;  q0 = (t - 34) * 128; }
    else             { st = 5312; S = 960;  q0 = (t - 42) * 128; }

    const int tid  = threadIdx.x;
    const int w    = tid >> 5;
    const int lane = tid & 31;
    const int g    = lane >> 2;
    const int q    = lane & 3;
    const int rowbase = w * 16;

    const float scale = 0.11785113019775793f;

    for (int s = tid; s < 128 * 9; s += 256) {
        int row = s / 9, c = s % 9;
        uint4 v = make_uint4(0, 0, 0, 0);
        if (q0 + row < S)
            v = *reinterpret_cast<const uint4*>(
                qkv + (size_t)(st + q0 + row) * QKVW + head * HDIM + c * 8);
        *reinterpret_cast<uint4*>(&Qs[row * FROW + c * 4]) = v;
    }
    for (int s = tid; s < 128 * 8; s += 256) Qs[(s >> 3) * FROW + 36 + (s & 7)] = 0;
    for (int s = tid; s < 64 * 8; s += 256) {
        Ks[(s >> 3) * FROW + 36 + (s & 7)] = 0;
        Vs[(s >> 3) * FROW + 36 + (s & 7)] = 0;
    }

    float m0 = -1e30f, m1 = -1e30f, l0 = 0.f, l1 = 0.f;
    float O[10][4];
#pragma unroll
    for (int i = 0; i < 10; i++)
#pragma unroll
        for (int r = 0; r < 4; r++) O[i][r] = 0.f;

    uint32_t smQ = (uint32_t)__cvta_generic_to_shared(Qs);
    uint32_t smK = (uint32_t)__cvta_generic_to_shared(Ks);
    uint32_t smV = (uint32_t)__cvta_generic_to_shared(Vs);
    const uint32_t qsb = smQ + (uint32_t)((rowbase + (lane & 15)) * FROW + (lane >> 4) * 4) * 4;
    const uint32_t ksb = smK + (uint32_t)((((lane & 7) + ((lane >> 4) << 3)) * FROW) +
                                          ((lane >> 3) & 1) * 4) * 4;
    const uint32_t vsb = smV + (uint32_t)(((lane & 15) * FROW) + (lane >> 4) * 4) * 4;

    const int nkv = S >> 6;
    for (int j = 0; j < nkv; j++) {
        __syncthreads();
        const int kv0 = j * 64;
        for (int s = tid; s < 64 * 9; s += 256) {
            int row = s / 9, c = s % 9;
            *reinterpret_cast<uint4*>(&Ks[row * FROW + c * 4]) =
                *reinterpret_cast<const uint4*>(
                    qkv + (size_t)(st + kv0 + row) * QKVW + DMODEL + head * HDIM + c * 8);
        }
        for (int s = tid; s < 64 * 9; s += 256) {
            int row = s / 9, c = s % 9;
            *reinterpret_cast<uint4*>(&Vs[row * FROW + c * 4]) =
                *reinterpret_cast<const uint4*>(
                    qkv + (size_t)(st + kv0 + row) * QKVW + 2 * DMODEL + head * HDIM + c * 8);
        }
        __syncthreads();

        float acc[8][4];
#pragma unroll
        for (int i = 0; i < 8; i++)
#pragma unroll
            for (int r = 0; r < 4; r++) acc[i][r] = 0.f;

#pragma unroll
        for (int kb = 0; kb < 5; kb++) {
            uint32_t af[4];
            asm volatile("ldmatrix.sync.aligned.m8n8.x4.shared.b16 {%0,%1,%2,%3}, [%4];"
                         : "=r"(af[0]), "=r"(af[1]), "=r"(af[2]), "=r"(af[3])
                         : "r"(qsb + (uint32_t)(kb * 8) * 4));
#pragma unroll
            for (int nt4 = 0; nt4 < 4; nt4++) {
                uint32_t bf[4];
                asm volatile("ldmatrix.sync.aligned.m8n8.x4.shared.b16 {%0,%1,%2,%3}, [%4];"
                             : "=r"(bf[0]), "=r"(bf[1]), "=r"(bf[2]), "=r"(bf[3])
                             : "r"(ksb + (uint32_t)(nt4 * 16 * FROW + kb * 8) * 4));
                mma_f16(acc[2 * nt4    ], af[0], af[1], af[2], af[3], bf[0], bf[1]);
                mma_f16(acc[2 * nt4 + 1], af[0], af[1], af[2], af[3], bf[2], bf[3]);
            }
        }
#pragma unroll
        for (int i = 0; i < 8; i++)
#pragma unroll
            for (int r = 0; r < 4; r++) acc[i][r] *= scale;

        float mx0 = -1e30f, mx1 = -1e30f;
#pragma unroll
        for (int i = 0; i < 8; i++) {
            mx0 = fmaxf(mx0, fmaxf(acc[i][0], acc[i][1]));
            mx1 = fmaxf(mx1, fmaxf(acc[i][2], acc[i][3]));
        }
        mx0 = fmaxf(mx0, __shfl_xor_sync(0xffffffffu, mx0, 1));
        mx0 = fmaxf(mx0, __shfl_xor_sync(0xffffffffu, mx0, 2));
        mx1 = fmaxf(mx1, __shfl_xor_sync(0xffffffffu, mx1, 1));
        mx1 = fmaxf(mx1, __shfl_xor_sync(0xffffffffu, mx1, 2));
        float mn0 = fmaxf(m0, mx0), mn1 = fmaxf(m1, mx1);
        float al0 = __expf(m0 - mn0), al1 = __expf(m1 - mn1);
        m0 = mn0; m1 = mn1;

        float rs0 = 0.f, rs1 = 0.f;
#pragma unroll
        for (int i = 0; i < 8; i++) {
            acc[i][0] = __expf(acc[i][0] - mn0);
            acc[i][1] = __expf(acc[i][1] - mn0);
            acc[i][2] = __expf(acc[i][2] - mn1);
            acc[i][3] = __expf(acc[i][3] - mn1);
            rs0 += acc[i][0] + acc[i][1];
            rs1 += acc[i][2] + acc[i][3];
        }
        rs0 += __shfl_xor_sync(0xffffffffu, rs0, 1);
        rs0 += __shfl_xor_sync(0xffffffffu, rs0, 2);
        rs1 += __shfl_xor_sync(0xffffffffu, rs1, 1);
        rs1 += __shfl_xor_sync(0xffffffffu, rs1, 2);
        l0 = l0 * al0 + rs0;
        l1 = l1 * al1 + rs1;

#pragma unroll
        for (int i = 0; i < 10; i++) {
            O[i][0] *= al0; O[i][1] *= al0;
            O[i][2] *= al1; O[i][3] *= al1;
        }

        uint32_t pa[4][4];
#pragma unroll
        for (int kb = 0; kb < 4; kb++) {
            pa[kb][0] = pack_h2(acc[2 * kb][0],     acc[2 * kb][1]);
            pa[kb][1] = pack_h2(acc[2 * kb][2],     acc[2 * kb][3]);
            pa[kb][2] = pack_h2(acc[2 * kb + 1][0], acc[2 * kb + 1][1]);
            pa[kb][3] = pack_h2(acc[2 * kb + 1][2], acc[2 * kb + 1][3]);
        }

#pragma unroll
        for (int kb = 0; kb < 4; kb++) {
#pragma unroll
            for (int vt = 0; vt < 5; vt++) {
                uint32_t bf[4];
                asm volatile("ldmatrix.sync.aligned.m8n8.x4.trans.shared.b16 {%0,%1,%2,%3}, [%4];"
                             : "=r"(bf[0]), "=r"(bf[1]), "=r"(bf[2]), "=r"(bf[3])
                             : "r"(vsb + (uint32_t)(kb * 16 * FROW + vt * 8) * 4));
                mma_f16(O[2 * vt    ], pa[kb][0], pa[kb][1], pa[kb][2], pa[kb][3], bf[0], bf[1]);
                mma_f16(O[2 * vt + 1], pa[kb][0], pa[kb][1], pa[kb][2], pa[kb][3], bf[2], bf[3]);
            }
        }
    }

#pragma unroll
    for (int h = 0; h < 2; h++) {
        int r = rowbase + g + 8 * h;
        if (q0 + r >= S) continue;
        float inv = 1.0f / (h == 0 ? l0 : l1);
#pragma unroll
        for (int ntl = 0; ntl < 9; ntl++) {
            int c = ntl * 8 + 2 * q;
            __half2 hv = __floats2half2_rn(O[ntl][2 * h] * inv, O[ntl][2 * h + 1] * inv);
            *reinterpret_cast<__half2*>(
                attn + (size_t)(st + q0 + r) * DMODEL + head * HDIM + c) = hv;
        }
    }
}

// ---------------------------------------------------------------------------
// Host launcher
// ---------------------------------------------------------------------------
#define SYMF(p, s) do { void* _t; cudaGetSymbolAddress(&_t, s); p = (float*)_t; } while (0)
#define SYMH(p, s) do { void* _t; cudaGetSymbolAddress(&_t, s); p = (__half*)_t; } while (0)

static inline dim3 ggrid3(int Md, int Nd) {
    return dim3((Nd + 127) / 128, (Md + 127) / 128);
}

extern "C" void kernel_launch(void* const* d_in, const int* in_sizes, int n_in,
                              void* d_out, int out_size)
{
    (void)in_sizes; (void)n_in; (void)out_size;
    const float* pixel    = (const float*)d_in[0];
    const float* patch_w  = (const float*)d_in[2];
    const float* patch_b  = (const float*)d_in[3];
    const float* pos_tab  = (const float*)d_in[4];
    const float* ln1_s    = (const float*)d_in[5];
    const float* ln1_b    = (const float*)d_in[6];
    const float* qkv_w    = (const float*)d_in[7];
    const float* qkv_b    = (const float*)d_in[8];
    const float* proj_w   = (const float*)d_in[9];
    const float* proj_b   = (const float*)d_in[10];
    const float* ln2_s    = (const float*)d_in[11];
    const float* ln2_b    = (const float*)d_in[12];
    const float* fc1_w    = (const float*)d_in[13];
    const float* fc1_b    = (const float*)d_in[14];
    const float* fc2_w    = (const float*)d_in[15];
    const float* fc2_b    = (const float*)d_in[16];
    const float* m_ln_s   = (const float*)d_in[17];
    const float* m_ln_b   = (const float*)d_in[18];
    const float* m_fc1_w  = (const float*)d_in[19];
    const float* m_fc1_b  = (const float*)d_in[20];
    const float* m_fc2_w  = (const float*)d_in[21];
    const float* m_fc2_b  = (const float*)d_in[22];
    float* out = (float*)d_out;

    float *x;
    __half *pix, *hh, *qkvh, *attnh, *mlph, *wt;
    SYMF(x, g_x);
    SYMH(pix, g_pix); SYMH(hh, g_hh); SYMH(qkvh, g_qkvh);
    SYMH(attnh, g_attnh); SYMH(mlph, g_mlph); SYMH(wt, g_wt);

    static bool attr_set = false;
    if (!attr_set) {
        cudaFuncSetAttribute(gemm3<EPI_BIAS, false>,
                             cudaFuncAttributeMaxDynamicSharedMemorySize, G4_SMEM);
        cudaFuncSetAttribute(gemm3<EPI_BIAS, true>,
                             cudaFuncAttributeMaxDynamicSharedMemorySize, G4_SMEM);
        cudaFuncSetAttribute(gemm3<EPI_BIAS_GELU, true>,
                             cudaFuncAttributeMaxDynamicSharedMemorySize, G4_SMEM);
        cudaFuncSetAttribute(gemm3<EPI_BIAS_RES, false>,
                             cudaFuncAttributeMaxDynamicSharedMemorySize, G4_SMEM);
        cudaFuncSetAttribute(gemm3<EPI_POS, false>,
                             cudaFuncAttributeMaxDynamicSharedMemorySize, G4_SMEM);
        attr_set = true;
    }

    // ---- fused fp32->fp16 conversion (single launch, all streams)
    {
        ConvJobs J;
        const float* srcs[NSEG] = {
            pixel, patch_w,
            qkv_w,  qkv_w  + SZ_QKV,
            proj_w, proj_w + SZ_PROJ,
            fc1_w,  fc1_w  + SZ_FC1,
            fc2_w,  fc2_w  + SZ_FC2,
            m_fc1_w, m_fc2_w, nullptr };
        __half* dsts[NSEG] = {
            pix, wt + OFF_PATCH,
            wt + OFF_QKV,  wt + OFF_QKV + SZ_QKV,
            wt + OFF_PROJ, wt + OFF_PROJ + SZ_PROJ,
            wt + OFF_FC1,  wt + OFF_FC1 + SZ_FC1,
            wt + OFF_FC2,  wt + OFF_FC2 + SZ_FC2,
            wt + OFF_MFC1, wt + OFF_MFC2, nullptr };
        long long sizes[NSEG] = {
            (long long)NTOK * CIN, (long long)SZ_PATCH,
            (long long)SZ_QKV, (long long)SZ_QKV,
            (long long)SZ_PROJ, (long long)SZ_PROJ,
            (long long)SZ_FC1, (long long)SZ_FC1,
            (long long)SZ_FC2, (long long)SZ_FC2,
            (long long)SZ_MFC1, (long long)SZ_MFC2, 0 };
        srcs[12]  = m_fc2_w;
        dsts[12]  = wt + OFF_MFC2;
        int off = 0;
        for (int s = 0; s < NSEG; s++) {
            J.src[s] = (const float4*)srcs[s];
            J.dst[s] = (uint2*)dsts[s];
            J.off[s] = off;
            off += (int)(sizes[s] / 4);
        }
        J.off[NSEG] = off;
        convall<<<(off + 255) / 256, 256>>>(J, off);
    }

    // Patch embed + bias + pos-embed -> x (fp32) in one kernel
    gemm3<EPI_POS, false><<<ggrid3(NTOK, DMODEL), 256, G4_SMEM>>>(
        pix, CIN, wt + OFF_PATCH, DMODEL, x, DMODEL,
        patch_b, nullptr, 0, NTOK, DMODEL, CIN, pos_tab);

    for (int l = 0; l < 2; l++) {
        ln_h<<<NTOK, 288>>>(x, hh, ln1_s + l * DMODEL, ln1_b + l * DMODEL);

        gemm3<EPI_BIAS, true><<<ggrid3(NTOK, QKVW), 256, G4_SMEM>>>(
            hh, DMODEL, wt + OFF_QKV + l * SZ_QKV, QKVW, qkvh, QKVW,
            qkv_b + (size_t)l * QKVW, nullptr, 0, NTOK, QKVW, DMODEL, nullptr);

        rope2<<<NTOK, 576>>>();

        flash_h<<<dim3(50, HEADS), 256>>>(qkvh, attnh);

        gemm3<EPI_BIAS_RES, false><<<ggrid3(NTOK, DMODEL), 256, G4_SMEM>>>(
            attnh, DMODEL, wt + OFF_PROJ + l * SZ_PROJ, DMODEL, x, DMODEL,
            proj_b + (size_t)l * DMODEL, x, DMODEL, NTOK, DMODEL, DMODEL, nullptr);

        ln_h<<<NTOK, 288>>>(x, hh, ln2_s + l * DMODEL, ln2_b + l * DMODEL);

        gemm3<EPI_BIAS_GELU, true><<<ggrid3(NTOK, IDIM), 256, G4_SMEM>>>(
            hh, DMODEL, wt + OFF_FC1 + l * SZ_FC1, IDIM, mlph, IDIM,
            fc1_b + (size_t)l * IDIM, nullptr, 0, NTOK, IDIM, DMODEL, nullptr);

        gemm3<EPI_BIAS_RES, false><<<ggrid3(NTOK, DMODEL), 256, G4_SMEM>>>(
            mlph, IDIM, wt + OFF_FC2 + l * SZ_FC2, DMODEL, x, DMODEL,
            fc2_b + (size_t)l * DMODEL, x, DMODEL, NTOK, DMODEL, IDIM, nullptr);
    }

    // merger
    ln_h<<<NTOK, 288>>>(x, hh, m_ln_s, m_ln_b);   // hh viewed as [1568][4608]

    gemm3<EPI_BIAS_GELU, true><<<ggrid3(MROWS, MD4), 256, G4_SMEM>>>(
        hh, MD4, wt + OFF_MFC1, MD4, mlph, MD4,
        m_fc1_b, nullptr, 0, MROWS, MD4, MD4, nullptr);

    gemm3<EPI_BIAS, false><<<ggrid3(MROWS, DOUT), 256, G4_SMEM>>>(
        mlph, MD4, wt + OFF_MFC2, DOUT, out, DOUT,
        m_fc2_b, nullptr, 0, MROWS, DOUT, MD4, nullptr);
}

// round 17
// speedup vs baseline: 1.0113x; 1.0072x over previous
#include <cuda_runtime.h>
#include <cuda_fp16.h>
#include <math.h>
#include <stdint.h>

// ---------------------------------------------------------------------------
// Problem constants (GRID fixed: [[1,48,48],[1,32,64],[2,24,40]])
// ---------------------------------------------------------------------------
#define NTOK    6272
#define DMODEL  1152
#define HEADS   16
#define HDIM    72
#define IDIM    4304
#define DOUT    2048
#define MROWS   1568
#define MD4     4608
#define QKVW    3456
#define CIN     1536

// ---------------------------------------------------------------------------
// Scratch buffers
// ---------------------------------------------------------------------------
__device__ float  g_x    [NTOK * DMODEL];        // residual (fp32)
__device__ __half g_pix  [NTOK * CIN];           // pixel fp16
__device__ __half g_hh   [NTOK * DMODEL];        // LN out fp16
__device__ __half g_qkvh [NTOK * QKVW];          // qkv fp16
__device__ __half g_attnh[NTOK * DMODEL];        // attn out fp16
__device__ __half g_mlph [NTOK * IDIM];          // mlp hidden fp16

// fp16 weights, natural [K,N] layout (no transpose)
#define SZ_PATCH (1536ULL * 1152)
#define SZ_QKV   (1152ULL * 3456)
#define SZ_PROJ  (1152ULL * 1152)
#define SZ_FC1   (1152ULL * 4304)
#define SZ_FC2   (4304ULL * 1152)
#define SZ_MFC1  (4608ULL * 4608)
#define SZ_MFC2  (4608ULL * 2048)
#define OFF_PATCH 0ULL
#define OFF_QKV   (OFF_PATCH + SZ_PATCH)
#define OFF_PROJ  (OFF_QKV + 2 * SZ_QKV)
#define OFF_FC1   (OFF_PROJ + 2 * SZ_PROJ)
#define OFF_FC2   (OFF_FC1 + 2 * SZ_FC1)
#define OFF_MFC1  (OFF_FC2 + 2 * SZ_FC2)
#define OFF_MFC2  (OFF_MFC1 + SZ_MFC1)
#define WT_TOTAL  (OFF_MFC2 + SZ_MFC2)
__device__ __half g_wt[WT_TOTAL];

// ---------------------------------------------------------------------------
__device__ __forceinline__ void token_pos(int n, int& row, int& col, int& ih, int& iw)
{
    int local, h, w;
    if (n < 2304)      { local = n;          h = 48; w = 48; }
    else if (n < 4352) { local = n - 2304;   h = 32; w = 64; }
    else               { local = n - 4352;   h = 24; w = 40; }
    int rem = local % (h * w);
    int wb_cnt = w >> 1;
    int blk = rem >> 2, within = rem & 3;
    int hb = blk / wb_cnt, wb = blk % wb_cnt;
    row = hb * 2 + (within >> 1);
    col = wb * 2 + (within & 1);
    ih = h; iw = w;
}

// ---------------------------------------------------------------------------
// Fused fp32->fp16 convert for ALL prep streams in one launch.
// ---------------------------------------------------------------------------
#define NSEG 13
struct ConvJobs {
    const float4* src[NSEG];
    uint2*        dst[NSEG];
    int           off[NSEG + 1];
};

__global__ void convall(ConvJobs J, int total)
{
    int i = blockIdx.x * blockDim.x + threadIdx.x;
    if (i >= total) return;
    int s = 0;
#pragma unroll
    for (int k = 1; k < NSEG; k++) s += (i >= J.off[k]) ? 1 : 0;
    int local = i - J.off[s];
    float4 v = J.src[s][local];
    __half2 lo = __floats2half2_rn(v.x, v.y);
    __half2 hi = __floats2half2_rn(v.z, v.w);
    J.dst[s][local] =
        make_uint2(*reinterpret_cast<uint32_t*>(&lo), *reinterpret_cast<uint32_t*>(&hi));
}

__device__ __forceinline__ float warp_sum(float v)
{
#pragma unroll
    for (int o = 16; o > 0; o >>= 1) v += __shfl_xor_sync(0xffffffffu, v, o);
    return v;
}

// LayerNorm fp32 in -> fp16 out; single-pass (sum + sumsq together)
__global__ void ln_h(const float* __restrict__ in, __half* __restrict__ out,
                     const float* __restrict__ s, const float* __restrict__ b)
{
    __shared__ float sh[9], sh2[9];
    __shared__ float stat[2];
    int n = blockIdx.x;
    const float4* xr4 = reinterpret_cast<const float4*>(in + (size_t)n * DMODEL);
    int t = threadIdx.x, wid = t >> 5, lane = t & 31;

    float4 v = xr4[t];
    float lsum = v.x + v.y + v.z + v.w;
    float lsq  = v.x * v.x + v.y * v.y + v.z * v.z + v.w * v.w;
    float ws = warp_sum(lsum);
    float wq = warp_sum(lsq);
    if (lane == 0) { sh[wid] = ws; sh2[wid] = wq; }
    __syncthreads();
    if (t == 0) {
        float tot = 0.f, totq = 0.f;
#pragma unroll
        for (int i = 0; i < 9; i++) { tot += sh[i]; totq += sh2[i]; }
        float mu = tot * (1.0f / DMODEL);
        float var = totq * (1.0f / DMODEL) - mu * mu;
        stat[0] = mu;
        stat[1] = rsqrtf(var + 1e-6f);
    }
    __syncthreads();
    float mu = stat[0], r = stat[1];
    float4 s4 = reinterpret_cast<const float4*>(s)[t];
    float4 b4 = reinterpret_cast<const float4*>(b)[t];
    __half2 p0 = __floats2half2_rn((v.x - mu) * r * s4.x + b4.x,
                                   (v.y - mu) * r * s4.y + b4.y);
    __half2 p1 = __floats2half2_rn((v.z - mu) * r * s4.z + b4.z,
                                   (v.w - mu) * r * s4.w + b4.w);
    reinterpret_cast<uint2*>(out + (size_t)n * DMODEL)[t] =
        make_uint2(*reinterpret_cast<uint32_t*>(&p0), *reinterpret_cast<uint32_t*>(&p1));
}

// RoPE in-place on fp16 qkv, cos/sin computed in-kernel (smem broadcast)
__global__ void rope2()
{
    __shared__ float cs[36], sn[36];
    int n = blockIdx.x;
    int t = threadIdx.x;
    if (t < 36) {
        int row, col, ih, iw;
        token_pos(n, row, col, ih, iw);
        int j = (t < 18) ? t : t - 18;
        float p = (t < 18) ? (float)row : (float)col;
        float inv = __expf(-(float)j * 0.5117865387079628f);   // 10000^{-j/18}
        float ang = p * inv;
        cs[t] = cosf(ang);
        sn[t] = sinf(ang);
    }
    __syncthreads();
    int h = t / 36, d = t % 36;
    float c = cs[d], s = sn[d];
    __half* q = g_qkvh + (size_t)n * QKVW + h * HDIM;
    __half* k = q + DMODEL;
    float q0 = __half2float(q[d]), q1 = __half2float(q[d + 36]);
    q[d]      = __float2half_rn(q0 * c - q1 * s);
    q[d + 36] = __float2half_rn(q1 * c + q0 * s);
    float k0 = __half2float(k[d]), k1 = __half2float(k[d + 36]);
    k[d]      = __float2half_rn(k0 * c - k1 * s);
    k[d + 36] = __float2half_rn(k1 * c + k0 * s);
}

// ---------------------------------------------------------------------------
// mma / misc helpers
// ---------------------------------------------------------------------------
__device__ __forceinline__ void mma_f16(float c[4],
                                        uint32_t a0, uint32_t a1, uint32_t a2, uint32_t a3,
                                        uint32_t b0, uint32_t b1)
{
    asm volatile(
        "mma.sync.aligned.m16n8k16.row.col.f32.f16.f16.f32 "
        "{%0,%1,%2,%3}, {%4,%5,%6,%7}, {%8,%9}, {%0,%1,%2,%3};\n"
        : "+f"(c[0]), "+f"(c[1]), "+f"(c[2]), "+f"(c[3])
        : "r"(a0), "r"(a1), "r"(a2), "r"(a3), "r"(b0), "r"(b1));
}

// fast gelu: HW tanh approx (MUFU.TANH)
__device__ __forceinline__ float gelu_tanh(float x)
{
    float u = 0.7978845608028654f * (x + 0.044715f * x * x * x);
    float t;
    asm("tanh.approx.f32 %0, %1;" : "=f"(t) : "f"(u));
    return 0.5f * x * (1.f + t);
}

__device__ __forceinline__ uint32_t pack_h2(float lo, float hi)
{
    __half2 h = __floats2half2_rn(lo, hi);
    return *reinterpret_cast<uint32_t*>(&h);
}

// ---------------------------------------------------------------------------
// GEMM v5: A fp16 [M,K] row-major, B fp16 [K,N] row-major, C fp32 or fp16.
//   Block 128x128, BK=64, 3 stages (dynamic smem), cp.async wait_group 1.
//   8 warps 2(M) x 4(N), warp tile 64x32.  64 MMAs per barrier (2x R16).
//   A rows: 64 halfs padded to 72 (36 words; 36r mod 32 = 4r -> banks disjoint)
//   B rows: 128 halfs padded to 136 (68 words; verified layout)
//   Stage: A 128*36 + B 64*68 = 8960 words = 35840 B; 3 stages = 107520 B.
//   EPI_POS: fused bias + bilinear pos-embed add (patch embed only).
// ---------------------------------------------------------------------------
#define EPI_BIAS      1
#define EPI_BIAS_GELU 2
#define EPI_BIAS_RES  3
#define EPI_POS       4

#define G5_AST  36
#define G5_BST  68
#define G5_BOFF 4608
#define G5_STG  8960
#define G5_NSTG 3
#define G5_SMEM (G5_NSTG * G5_STG * 4)

template<int EPI, bool OUTH>
__global__ void __launch_bounds__(256, 2)
gemm3(const __half* __restrict__ A, int lda,
      const __half* __restrict__ B, int ldb,
      void* __restrict__ Cv, int ldc,
      const float* __restrict__ bias,
      const float* __restrict__ Res, int ldr,
      int Md, int Nd, int Kd,
      const float* __restrict__ ptab)
{
    extern __shared__ uint32_t smbuf[];

    const int tid  = threadIdx.x;
    const int brow = blockIdx.y * 128;
    const int bcol = blockIdx.x * 128;
    const int w    = tid >> 5;
    const int lane = tid & 31;
    const int g    = lane >> 2;
    const int q    = lane & 3;
    const int wm   = w & 1;
    const int wn   = w >> 1;

    uint32_t smbase = (uint32_t)__cvta_generic_to_shared(smbuf);

    // A loader: 4 chunks/thread/stage (128 rows x 64 halfs)
    int aok[4], ak8[4];
    uint32_t sa[4];
    const __half* ga[4];
#pragma unroll
    for (int i = 0; i < 4; i++) {
        int c = tid + i * 256;
        int row = c >> 3;                 // 0..127
        ak8[i] = (c & 7) * 8;             // 0..56
        aok[i] = (brow + row) < Md;
        sa[i] = smbase + (uint32_t)(row * G5_AST + (c & 7) * 4) * 4;
        ga[i] = A + (long long)(brow + row) * lda + ak8[i];
    }
    // B loader: 4 chunks/thread/stage (64 k-rows x 128 halfs)
    int bkr[4], bok[4];
    uint32_t sb[4];
    const __half* gb[4];
#pragma unroll
    for (int i = 0; i < 4; i++) {
        int c = tid + i * 256;
        bkr[i] = c >> 4;                  // 0..63
        int n8 = (c & 15) * 8;
        bok[i] = (bcol + n8) < Nd;
        sb[i] = smbase + (uint32_t)(G5_BOFF + bkr[i] * G5_BST + (c & 15) * 4) * 4;
        gb[i] = B + (long long)bkr[i] * ldb + bcol + n8;
    }

    float acc[4][4][4];
#pragma unroll
    for (int i = 0; i < 4; i++)
#pragma unroll
        for (int j = 0; j < 4; j++)
#pragma unroll
            for (int r = 0; r < 4; r++) acc[i][j][r] = 0.f;

    const int ntk = (Kd + 63) >> 6;

    auto load_stage = [&](int k0, int st) {
        uint32_t off = (uint32_t)(st * G5_STG) * 4;
#pragma unroll
        for (int i = 0; i < 4; i++) {
            int va = (aok[i] && (k0 + ak8[i]) < Kd) ? 16 : 0;
            asm volatile("cp.async.cg.shared.global [%0], [%1], 16, %2;"
                         :: "r"(sa[i] + off), "l"(ga[i] + k0), "r"(va));
        }
#pragma unroll
        for (int i = 0; i < 4; i++) {
            int vb = (bok[i] && (k0 + bkr[i]) < Kd) ? 16 : 0;
            asm volatile("cp.async.cg.shared.global [%0], [%1], 16, %2;"
                         :: "r"(sb[i] + off), "l"(gb[i] + (long long)k0 * ldb), "r"(vb));
        }
    };

    load_stage(0, 0);
    asm volatile("cp.async.commit_group;");
    if (ntk > 1) load_stage(64, 1);
    asm volatile("cp.async.commit_group;");

    const int a_row = wm * 64 + (lane & 15);
    const uint32_t abase = smbase + (uint32_t)(a_row * G5_AST + (lane >> 4) * 4) * 4;
    const uint32_t bbase = smbase + (uint32_t)G5_BOFF * 4 +
        (uint32_t)((lane & 15) * G5_BST * 4 + (wn * 32 + (lane >> 4) * 8) * 2);

    for (int kt = 0; kt < ntk; kt++) {
        asm volatile("cp.async.wait_group 1;");
        __syncthreads();
        int sti = kt % 3;
        uint32_t soff = (uint32_t)(sti * G5_STG) * 4;

#pragma unroll
        for (int kg = 0; kg < 4; kg++) {
            uint32_t akg = soff + (uint32_t)(kg * 8) * 4;                // +8 words in A row
            uint32_t bkg = soff + (uint32_t)(kg * 16 * G5_BST) * 4;      // +16 B rows

            uint32_t af[4][4], bf[2][4];
#pragma unroll
            for (int mt = 0; mt < 4; mt++)
                asm volatile("ldmatrix.sync.aligned.m8n8.x4.shared.b16 {%0,%1,%2,%3}, [%4];"
                             : "=r"(af[mt][0]), "=r"(af[mt][1]), "=r"(af[mt][2]), "=r"(af[mt][3])
                             : "r"(abase + akg + (uint32_t)(mt * 16 * G5_AST) * 4));
#pragma unroll
            for (int ng = 0; ng < 2; ng++)
                asm volatile("ldmatrix.sync.aligned.m8n8.x4.trans.shared.b16 {%0,%1,%2,%3}, [%4];"
                             : "=r"(bf[ng][0]), "=r"(bf[ng][1]), "=r"(bf[ng][2]), "=r"(bf[ng][3])
                             : "r"(bbase + bkg + (uint32_t)(ng * 32)));

#pragma unroll
            for (int mt = 0; mt < 4; mt++)
#pragma unroll
                for (int j = 0; j < 4; j++)
                    mma_f16(acc[mt][j],
                            af[mt][0], af[mt][1], af[mt][2], af[mt][3],
                            bf[j >> 1][(j & 1) * 2], bf[j >> 1][(j & 1) * 2 + 1]);
        }

        int ktn = kt + 2;
        if (ktn < ntk)
            load_stage(ktn * 64, ktn % 3);
        asm volatile("cp.async.commit_group;");
    }

    float*  Cf = (float*)Cv;
    __half* Ch = (__half*)Cv;
#pragma unroll
    for (int mt = 0; mt < 4; mt++) {
#pragma unroll
        for (int hh = 0; hh < 2; hh++) {
            int r = brow + wm * 64 + mt * 16 + g + 8 * hh;
            if (r >= Md) continue;

            const float *p00 = nullptr, *p01 = nullptr, *p10 = nullptr, *p11 = nullptr;
            float w00, w01, w10, w11;
            if (EPI == EPI_POS) {
                int prow, pcol, ih, iw;
                token_pos(r, prow, pcol, ih, iw);
                int hd = ih - 1, wd = iw - 1;
                int hnum = 47 * prow, wnum = 47 * pcol;
                int hf = hnum / hd, wf = wnum / wd;
                float dh = (float)(hnum - hf * hd) / (float)hd;
                float dw = (float)(wnum - wf * wd) / (float)wd;
                int hc = min(hf + 1, 47), wc = min(wf + 1, 47);
                w00 = (1.f - dh) * (1.f - dw);
                w01 = (1.f - dh) * dw;
                w10 = dh * (1.f - dw);
                w11 = dh * dw;
                p00 = ptab + (size_t)(hf * 48 + wf) * DMODEL;
                p01 = ptab + (size_t)(hf * 48 + wc) * DMODEL;
                p10 = ptab + (size_t)(hc * 48 + wf) * DMODEL;
                p11 = ptab + (size_t)(hc * 48 + wc) * DMODEL;
            }

#pragma unroll
            for (int j = 0; j < 4; j++) {
                int c = bcol + wn * 32 + j * 8 + 2 * q;
                if (c >= Nd) continue;
                float v0 = acc[mt][j][hh * 2];
                float v1 = acc[mt][j][hh * 2 + 1];
                v0 += bias[c]; v1 += bias[c + 1];
                if (EPI == EPI_BIAS_GELU) { v0 = gelu_tanh(v0); v1 = gelu_tanh(v1); }
                if (EPI == EPI_BIAS_RES)  {
                    v0 += Res[(long long)r * ldr + c];
                    v1 += Res[(long long)r * ldr + c + 1];
                }
                if (EPI == EPI_POS) {
                    v0 += p00[c] * w00 + p01[c] * w01 + p10[c] * w10 + p11[c] * w11;
                    v1 += p00[c + 1] * w00 + p01[c + 1] * w01 +
                          p10[c + 1] * w10 + p11[c + 1] * w11;
                }
                if (OUTH) {
                    __half2 hv = __floats2half2_rn(v0, v1);
                    *reinterpret_cast<__half2*>(Ch + (long long)r * ldc + c) = hv;
                } else {
                    *reinterpret_cast<float2*>(Cf + (long long)r * ldc + c) = make_float2(v0, v1);
                }
            }
        }
    }
}

// ---------------------------------------------------------------------------
// Fused flash attention v2 (unchanged — verified).
// ---------------------------------------------------------------------------
#define FROW 44

__global__ void __launch_bounds__(256, 2)
flash_h(const __half* __restrict__ qkv, __half* __restrict__ attn)
{
    __shared__ uint32_t Qs[128 * FROW];
    __shared__ uint32_t Ks[64 * FROW];
    __shared__ uint32_t Vs[64 * FROW];

    int t = blockIdx.x;
    int head = blockIdx.y;
    int st, S, q0;
    if (t < 18)      { st = 0;    S = 2304; q0 = t * 128; }
    else if (t < 34) { st = 2304; S = 2048; q0 = (t - 18) * 128; }
    else if (t < 42) { st = 4352; S = 960;  q0 = (t - 34) * 128; }
    else             { st = 5312; S = 960;  q0 = (t - 42) * 128; }

    const int tid  = threadIdx.x;
    const int w    = tid >> 5;
    const int lane = tid & 31;
    const int g    = lane >> 2;
    const int q    = lane & 3;
    const int rowbase = w * 16;

    const float scale = 0.11785113019775793f;

    for (int s = tid; s < 128 * 9; s += 256) {
        int row = s / 9, c = s % 9;
        uint4 v = make_uint4(0, 0, 0, 0);
        if (q0 + row < S)
            v = *reinterpret_cast<const uint4*>(
                qkv + (size_t)(st + q0 + row) * QKVW + head * HDIM + c * 8);
        *reinterpret_cast<uint4*>(&Qs[row * FROW + c * 4]) = v;
    }
    for (int s = tid; s < 128 * 8; s += 256) Qs[(s >> 3) * FROW + 36 + (s & 7)] = 0;
    for (int s = tid; s < 64 * 8; s += 256) {
        Ks[(s >> 3) * FROW + 36 + (s & 7)] = 0;
        Vs[(s >> 3) * FROW + 36 + (s & 7)] = 0;
    }

    float m0 = -1e30f, m1 = -1e30f, l0 = 0.f, l1 = 0.f;
    float O[10][4];
#pragma unroll
    for (int i = 0; i < 10; i++)
#pragma unroll
        for (int r = 0; r < 4; r++) O[i][r] = 0.f;

    uint32_t smQ = (uint32_t)__cvta_generic_to_shared(Qs);
    uint32_t smK = (uint32_t)__cvta_generic_to_shared(Ks);
    uint32_t smV = (uint32_t)__cvta_generic_to_shared(Vs);
    const uint32_t qsb = smQ + (uint32_t)((rowbase + (lane & 15)) * FROW + (lane >> 4) * 4) * 4;
    const uint32_t ksb = smK + (uint32_t)((((lane & 7) + ((lane >> 4) << 3)) * FROW) +
                                          ((lane >> 3) & 1) * 4) * 4;
    const uint32_t vsb = smV + (uint32_t)(((lane & 15) * FROW) + (lane >> 4) * 4) * 4;

    const int nkv = S >> 6;
    for (int j = 0; j < nkv; j++) {
        __syncthreads();
        const int kv0 = j * 64;
        for (int s = tid; s < 64 * 9; s += 256) {
            int row = s / 9, c = s % 9;
            *reinterpret_cast<uint4*>(&Ks[row * FROW + c * 4]) =
                *reinterpret_cast<const uint4*>(
                    qkv + (size_t)(st + kv0 + row) * QKVW + DMODEL + head * HDIM + c * 8);
        }
        for (int s = tid; s < 64 * 9; s += 256) {
            int row = s / 9, c = s % 9;
            *reinterpret_cast<uint4*>(&Vs[row * FROW + c * 4]) =
                *reinterpret_cast<const uint4*>(
                    qkv + (size_t)(st + kv0 + row) * QKVW + 2 * DMODEL + head * HDIM + c * 8);
        }
        __syncthreads();

        float acc[8][4];
#pragma unroll
        for (int i = 0; i < 8; i++)
#pragma unroll
            for (int r = 0; r < 4; r++) acc[i][r] = 0.f;

#pragma unroll
        for (int kb = 0; kb < 5; kb++) {
            uint32_t af[4];
            asm volatile("ldmatrix.sync.aligned.m8n8.x4.shared.b16 {%0,%1,%2,%3}, [%4];"
                         : "=r"(af[0]), "=r"(af[1]), "=r"(af[2]), "=r"(af[3])
                         : "r"(qsb + (uint32_t)(kb * 8) * 4));
#pragma unroll
            for (int nt4 = 0; nt4 < 4; nt4++) {
                uint32_t bf[4];
                asm volatile("ldmatrix.sync.aligned.m8n8.x4.shared.b16 {%0,%1,%2,%3}, [%4];"
                             : "=r"(bf[0]), "=r"(bf[1]), "=r"(bf[2]), "=r"(bf[3])
                             : "r"(ksb + (uint32_t)(nt4 * 16 * FROW + kb * 8) * 4));
                mma_f16(acc[2 * nt4    ], af[0], af[1], af[2], af[3], bf[0], bf[1]);
                mma_f16(acc[2 * nt4 + 1], af[0], af[1], af[2], af[3], bf[2], bf[3]);
            }
        }
#pragma unroll
        for (int i = 0; i < 8; i++)
#pragma unroll
            for (int r = 0; r < 4; r++) acc[i][r] *= scale;

        float mx0 = -1e30f, mx1 = -1e30f;
#pragma unroll
        for (int i = 0; i < 8; i++) {
            mx0 = fmaxf(mx0, fmaxf(acc[i][0], acc[i][1]));
            mx1 = fmaxf(mx1, fmaxf(acc[i][2], acc[i][3]));
        }
        mx0 = fmaxf(mx0, __shfl_xor_sync(0xffffffffu, mx0, 1));
        mx0 = fmaxf(mx0, __shfl_xor_sync(0xffffffffu, mx0, 2));
        mx1 = fmaxf(mx1, __shfl_xor_sync(0xffffffffu, mx1, 1));
        mx1 = fmaxf(mx1, __shfl_xor_sync(0xffffffffu, mx1, 2));
        float mn0 = fmaxf(m0, mx0), mn1 = fmaxf(m1, mx1);
        float al0 = __expf(m0 - mn0), al1 = __expf(m1 - mn1);
        m0 = mn0; m1 = mn1;

        float rs0 = 0.f, rs1 = 0.f;
#pragma unroll
        for (int i = 0; i < 8; i++) {
            acc[i][0] = __expf(acc[i][0] - mn0);
            acc[i][1] = __expf(acc[i][1] - mn0);
            acc[i][2] = __expf(acc[i][2] - mn1);
            acc[i][3] = __expf(acc[i][3] - mn1);
            rs0 += acc[i][0] + acc[i][1];
            rs1 += acc[i][2] + acc[i][3];
        }
        rs0 += __shfl_xor_sync(0xffffffffu, rs0, 1);
        rs0 += __shfl_xor_sync(0xffffffffu, rs0, 2);
        rs1 += __shfl_xor_sync(0xffffffffu, rs1, 1);
        rs1 += __shfl_xor_sync(0xffffffffu, rs1, 2);
        l0 = l0 * al0 + rs0;
        l1 = l1 * al1 + rs1;

#pragma unroll
        for (int i = 0; i < 10; i++) {
            O[i][0] *= al0; O[i][1] *= al0;
            O[i][2] *= al1; O[i][3] *= al1;
        }

        uint32_t pa[4][4];
#pragma unroll
        for (int kb = 0; kb < 4; kb++) {
            pa[kb][0] = pack_h2(acc[2 * kb][0],     acc[2 * kb][1]);
            pa[kb][1] = pack_h2(acc[2 * kb][2],     acc[2 * kb][3]);
            pa[kb][2] = pack_h2(acc[2 * kb + 1][0], acc[2 * kb + 1][1]);
            pa[kb][3] = pack_h2(acc[2 * kb + 1][2], acc[2 * kb + 1][3]);
        }

#pragma unroll
        for (int kb = 0; kb < 4; kb++) {
#pragma unroll
            for (int vt = 0; vt < 5; vt++) {
                uint32_t bf[4];
                asm volatile("ldmatrix.sync.aligned.m8n8.x4.trans.shared.b16 {%0,%1,%2,%3}, [%4];"
                             : "=r"(bf[0]), "=r"(bf[1]), "=r"(bf[2]), "=r"(bf[3])
                             : "r"(vsb + (uint32_t)(kb * 16 * FROW + vt * 8) * 4));
                mma_f16(O[2 * vt    ], pa[kb][0], pa[kb][1], pa[kb][2], pa[kb][3], bf[0], bf[1]);
                mma_f16(O[2 * vt + 1], pa[kb][0], pa[kb][1], pa[kb][2], pa[kb][3], bf[2], bf[3]);
            }
        }
    }

#pragma unroll
    for (int h = 0; h < 2; h++) {
        int r = rowbase + g + 8 * h;
        if (q0 + r >= S) continue;
        float inv = 1.0f / (h == 0 ? l0 : l1);
#pragma unroll
        for (int ntl = 0; ntl < 9; ntl++) {
            int c = ntl * 8 + 2 * q;
            __half2 hv = __floats2half2_rn(O[ntl][2 * h] * inv, O[ntl][2 * h + 1] * inv);
            *reinterpret_cast<__half2*>(
                attn + (size_t)(st + q0 + r) * DMODEL + head * HDIM + c) = hv;
        }
    }
}

// ---------------------------------------------------------------------------
// Host launcher
// ---------------------------------------------------------------------------
#define SYMF(p, s) do { void* _t; cudaGetSymbolAddress(&_t, s); p = (float*)_t; } while (0)
#define SYMH(p, s) do { void* _t; cudaGetSymbolAddress(&_t, s); p = (__half*)_t; } while (0)

static inline dim3 ggrid3(int Md, int Nd) {
    return dim3((Nd + 127) / 128, (Md + 127) / 128);
}

extern "C" void kernel_launch(void* const* d_in, const int* in_sizes, int n_in,
                              void* d_out, int out_size)
{
    (void)in_sizes; (void)n_in; (void)out_size;
    const float* pixel    = (const float*)d_in[0];
    const float* patch_w  = (const float*)d_in[2];
    const float* patch_b  = (const float*)d_in[3];
    const float* pos_tab  = (const float*)d_in[4];
    const float* ln1_s    = (const float*)d_in[5];
    const float* ln1_b    = (const float*)d_in[6];
    const float* qkv_w    = (const float*)d_in[7];
    const float* qkv_b    = (const float*)d_in[8];
    const float* proj_w   = (const float*)d_in[9];
    const float* proj_b   = (const float*)d_in[10];
    const float* ln2_s    = (const float*)d_in[11];
    const float* ln2_b    = (const float*)d_in[12];
    const float* fc1_w    = (const float*)d_in[13];
    const float* fc1_b    = (const float*)d_in[14];
    const float* fc2_w    = (const float*)d_in[15];
    const float* fc2_b    = (const float*)d_in[16];
    const float* m_ln_s   = (const float*)d_in[17];
    const float* m_ln_b   = (const float*)d_in[18];
    const float* m_fc1_w  = (const float*)d_in[19];
    const float* m_fc1_b  = (const float*)d_in[20];
    const float* m_fc2_w  = (const float*)d_in[21];
    const float* m_fc2_b  = (const float*)d_in[22];
    float* out = (float*)d_out;

    float *x;
    __half *pix, *hh, *qkvh, *attnh, *mlph, *wt;
    SYMF(x, g_x);
    SYMH(pix, g_pix); SYMH(hh, g_hh); SYMH(qkvh, g_qkvh);
    SYMH(attnh, g_attnh); SYMH(mlph, g_mlph); SYMH(wt, g_wt);

    static bool attr_set = false;
    if (!attr_set) {
        cudaFuncSetAttribute(gemm3<EPI_BIAS, false>,
                             cudaFuncAttributeMaxDynamicSharedMemorySize, G5_SMEM);
        cudaFuncSetAttribute(gemm3<EPI_BIAS, true>,
                             cudaFuncAttributeMaxDynamicSharedMemorySize, G5_SMEM);
        cudaFuncSetAttribute(gemm3<EPI_BIAS_GELU, true>,
                             cudaFuncAttributeMaxDynamicSharedMemorySize, G5_SMEM);
        cudaFuncSetAttribute(gemm3<EPI_BIAS_RES, false>,
                             cudaFuncAttributeMaxDynamicSharedMemorySize, G5_SMEM);
        cudaFuncSetAttribute(gemm3<EPI_POS, false>,
                             cudaFuncAttributeMaxDynamicSharedMemorySize, G5_SMEM);
        attr_set = true;
    }

    // ---- fused fp32->fp16 conversion (single launch, all streams)
    {
        ConvJobs J;
        const float* srcs[NSEG] = {
            pixel, patch_w,
            qkv_w,  qkv_w  + SZ_QKV,
            proj_w, proj_w + SZ_PROJ,
            fc1_w,  fc1_w  + SZ_FC1,
            fc2_w,  fc2_w  + SZ_FC2,
            m_fc1_w, m_fc2_w, nullptr };
        __half* dsts[NSEG] = {
            pix, wt + OFF_PATCH,
            wt + OFF_QKV,  wt + OFF_QKV + SZ_QKV,
            wt + OFF_PROJ, wt + OFF_PROJ + SZ_PROJ,
            wt + OFF_FC1,  wt + OFF_FC1 + SZ_FC1,
            wt + OFF_FC2,  wt + OFF_FC2 + SZ_FC2,
            wt + OFF_MFC1, wt + OFF_MFC2, nullptr };
        long long sizes[NSEG] = {
            (long long)NTOK * CIN, (long long)SZ_PATCH,
            (long long)SZ_QKV, (long long)SZ_QKV,
            (long long)SZ_PROJ, (long long)SZ_PROJ,
            (long long)SZ_FC1, (long long)SZ_FC1,
            (long long)SZ_FC2, (long long)SZ_FC2,
            (long long)SZ_MFC1, (long long)SZ_MFC2, 0 };
        srcs[12]  = m_fc2_w;
        dsts[12]  = wt + OFF_MFC2;
        int off = 0;
        for (int s = 0; s < NSEG; s++) {
            J.src[s] = (const float4*)srcs[s];
            J.dst[s] = (uint2*)dsts[s];
            J.off[s] = off;
            off += (int)(sizes[s] / 4);
        }
        J.off[NSEG] = off;
        convall<<<(off + 255) / 256, 256>>>(J, off);
    }

    // Patch embed + bias + pos-embed -> x (fp32) in one kernel
    gemm3<EPI_POS, false><<<ggrid3(NTOK, DMODEL), 256, G5_SMEM>>>(
        pix, CIN, wt + OFF_PATCH, DMODEL, x, DMODEL,
        patch_b, nullptr, 0, NTOK, DMODEL, CIN, pos_tab);

    for (int l = 0; l < 2; l++) {
        ln_h<<<NTOK, 288>>>(x, hh, ln1_s + l * DMODEL, ln1_b + l * DMODEL);

        gemm3<EPI_BIAS, true><<<ggrid3(NTOK, QKVW), 256, G5_SMEM>>>(
            hh, DMODEL, wt + OFF_QKV + l * SZ_QKV, QKVW, qkvh, QKVW,
            qkv_b + (size_t)l * QKVW, nullptr, 0, NTOK, QKVW, DMODEL, nullptr);

        rope2<<<NTOK, 576>>>();

        flash_h<<<dim3(50, HEADS), 256>>>(qkvh, attnh);

        gemm3<EPI_BIAS_RES, false><<<ggrid3(NTOK, DMODEL), 256, G5_SMEM>>>(
            attnh, DMODEL, wt + OFF_PROJ + l * SZ_PROJ, DMODEL, x, DMODEL,
            proj_b + (size_t)l * DMODEL, x, DMODEL, NTOK, DMODEL, DMODEL, nullptr);

        ln_h<<<NTOK, 288>>>(x, hh, ln2_s + l * DMODEL, ln2_b + l * DMODEL);

        gemm3<EPI_BIAS_GELU, true><<<ggrid3(NTOK, IDIM), 256, G5_SMEM>>>(
            hh, DMODEL, wt + OFF_FC1 + l * SZ_FC1, IDIM, mlph, IDIM,
            fc1_b + (size_t)l * IDIM, nullptr, 0, NTOK, IDIM, DMODEL, nullptr);

        gemm3<EPI_BIAS_RES, false><<<ggrid3(NTOK, DMODEL), 256, G5_SMEM>>>(
            mlph, IDIM, wt + OFF_FC2 + l * SZ_FC2, DMODEL, x, DMODEL,
            fc2_b + (size_t)l * DMODEL, x, DMODEL, NTOK, DMODEL, IDIM, nullptr);
    }

    // merger
    ln_h<<<NTOK, 288>>>(x, hh, m_ln_s, m_ln_b);   // hh viewed as [1568][4608]

    gemm3<EPI_BIAS_GELU, true><<<ggrid3(MROWS, MD4), 256, G5_SMEM>>>(
        hh, MD4, wt + OFF_MFC1, MD4, mlph, MD4,
        m_fc1_b, nullptr, 0, MROWS, MD4, MD4, nullptr);

    gemm3<EPI_BIAS, false><<<ggrid3(MROWS, DOUT), 256, G5_SMEM>>>(
        mlph, MD4, wt + OFF_MFC2, DOUT, out, DOUT,
        m_fc2_b, nullptr, 0, MROWS, DOUT, MD4, nullptr);
}